// round 1
// baseline (speedup 1.0000x reference)
#include <cuda_runtime.h>
#include <math.h>

#define HIDN 4096
#define NH   32
#define NKV  8
#define HD   128
#define BB   4
#define QL   1024
#define PAST 1024
#define SKV  2048
#define MROWS (BB*QL)   /* 4096 */

// -------- scratch (device globals; no allocation allowed) --------
__device__ float g_q[(size_t)MROWS * HIDN];        // [B*Sq, H*D]
__device__ float g_k[(size_t)MROWS * (NKV * HD)];  // [B*Sq, Hkv*D]
__device__ float g_v[(size_t)MROWS * (NKV * HD)];
__device__ float g_att[(size_t)MROWS * HIDN];      // [B*Sq, H*D]

// ======================================================================
// GEMM NT: C[m,n] = alpha * ( sum_k A[m,k]*W[n,k] + bias[n] )
// A: [M,K] row-major, W: [N,K] row-major. M,N mult of 128, K mult of 16.
// ======================================================================
__global__ __launch_bounds__(256) void gemm_nt(
    const float* __restrict__ A, const float* __restrict__ W,
    const float* __restrict__ bias, float* __restrict__ C,
    int M, int N, int K, float alpha)
{
    __shared__ float As[16][132];
    __shared__ float Bs[16][132];

    const int tid = threadIdx.x;
    const int bm = blockIdx.y * 128;
    const int bn = blockIdx.x * 128;

    const int lr = tid >> 2;          // 0..63
    const int lc = (tid & 3) << 2;    // 0,4,8,12

    const int tm = (tid >> 4) << 3;   // row base, step 8
    const int tn = (tid & 15) << 2;   // col base, step 4 (cols tn..tn+3 and 64+tn..)

    const float* Ag = A + (size_t)(bm + lr) * K + lc;
    const float* Bg = W + (size_t)(bn + lr) * K + lc;
    const size_t rowskip = (size_t)64 * K;

    float acc[8][8];
#pragma unroll
    for (int i = 0; i < 8; ++i)
#pragma unroll
        for (int j = 0; j < 8; ++j) acc[i][j] = 0.f;

    float4 pa0 = *(const float4*)(Ag);
    float4 pa1 = *(const float4*)(Ag + rowskip);
    float4 pb0 = *(const float4*)(Bg);
    float4 pb1 = *(const float4*)(Bg + rowskip);

    const int steps = K >> 4;
    for (int t = 0; t < steps; ++t) {
        As[lc + 0][lr]      = pa0.x; As[lc + 1][lr]      = pa0.y;
        As[lc + 2][lr]      = pa0.z; As[lc + 3][lr]      = pa0.w;
        As[lc + 0][lr + 64] = pa1.x; As[lc + 1][lr + 64] = pa1.y;
        As[lc + 2][lr + 64] = pa1.z; As[lc + 3][lr + 64] = pa1.w;
        Bs[lc + 0][lr]      = pb0.x; Bs[lc + 1][lr]      = pb0.y;
        Bs[lc + 2][lr]      = pb0.z; Bs[lc + 3][lr]      = pb0.w;
        Bs[lc + 0][lr + 64] = pb1.x; Bs[lc + 1][lr + 64] = pb1.y;
        Bs[lc + 2][lr + 64] = pb1.z; Bs[lc + 3][lr + 64] = pb1.w;
        __syncthreads();

        if (t + 1 < steps) {
            const float* An = Ag + (size_t)(t + 1) * 16;
            const float* Bn = Bg + (size_t)(t + 1) * 16;
            pa0 = *(const float4*)(An);
            pa1 = *(const float4*)(An + rowskip);
            pb0 = *(const float4*)(Bn);
            pb1 = *(const float4*)(Bn + rowskip);
        }

#pragma unroll
        for (int k = 0; k < 16; ++k) {
            float4 a0 = *(const float4*)&As[k][tm];
            float4 a1 = *(const float4*)&As[k][tm + 4];
            float4 b0 = *(const float4*)&Bs[k][tn];
            float4 b1 = *(const float4*)&Bs[k][tn + 64];
            float av[8] = {a0.x, a0.y, a0.z, a0.w, a1.x, a1.y, a1.z, a1.w};
            float bv[8] = {b0.x, b0.y, b0.z, b0.w, b1.x, b1.y, b1.z, b1.w};
#pragma unroll
            for (int i = 0; i < 8; ++i)
#pragma unroll
                for (int j = 0; j < 8; ++j) acc[i][j] += av[i] * bv[j];
        }
        __syncthreads();
    }

    float bsv[8];
#pragma unroll
    for (int j = 0; j < 4; ++j) {
        bsv[j]     = bias[bn + tn + j];
        bsv[4 + j] = bias[bn + 64 + tn + j];
    }
#pragma unroll
    for (int i = 0; i < 8; ++i) {
        size_t row = (size_t)(bm + tm + i);
        float4 o0, o1;
        o0.x = alpha * (acc[i][0] + bsv[0]);
        o0.y = alpha * (acc[i][1] + bsv[1]);
        o0.z = alpha * (acc[i][2] + bsv[2]);
        o0.w = alpha * (acc[i][3] + bsv[3]);
        o1.x = alpha * (acc[i][4] + bsv[4]);
        o1.y = alpha * (acc[i][5] + bsv[5]);
        o1.z = alpha * (acc[i][6] + bsv[6]);
        o1.w = alpha * (acc[i][7] + bsv[7]);
        *(float4*)&C[row * N + bn + tn]      = o0;
        *(float4*)&C[row * N + bn + 64 + tn] = o1;
    }
}

// ======================================================================
// Flash attention: one CTA per (b, h, 64-query tile). KV tile = 64.
// Q,K transposed in smem (conflict-free), V row-major, P transposed.
// ======================================================================
#define QT 64
#define KT 64
#define SQS 68    /* stride of transposed Qs/Ks/Pt rows */
#define SVS 132   /* stride of Vs rows */
#define ATTN_SMEM_FLOATS (128*SQS /*Qs*/ + 128*SQS /*Ks*/ + KT*SVS /*Vs*/ + KT*SQS /*Pt*/)
#define ATTN_SMEM_BYTES (ATTN_SMEM_FLOATS * 4)

__global__ __launch_bounds__(256) void attn_kernel(
    const float* __restrict__ pastk, const float* __restrict__ pastv,
    const int* __restrict__ mask)
{
    extern __shared__ float sm[];
    float* Qs = sm;                    // [128][SQS]  Qs[d][i]
    float* Ks = Qs + 128 * SQS;        // [128][SQS]  Ks[d][j]
    float* Vs = Ks + 128 * SQS;        // [KT][SVS]   Vs[j][c]
    float* Pt = Vs + KT * SVS;         // [KT][SQS]   Pt[j][i]
    __shared__ float Ms[KT];

    const int tid = threadIdx.x;
    const int qt = blockIdx.x, h = blockIdx.y, b = blockIdx.z;
    const int hkv = h >> 2;
    const int q0 = qt * QT;

    const int ty4 = (tid >> 4) << 2;   // query-row base (4 rows)
    const int tx4 = (tid & 15) << 2;   // col base (cols tx4.. and 64+tx4..)

    // ---- load Q tile transposed ----
    for (int e = tid; e < QT * 32; e += 256) {
        int r = e >> 5, c4 = (e & 31) << 2;
        const float4 v = *(const float4*)(g_q + (size_t)(b * QL + q0 + r) * HIDN + h * HD + c4);
        Qs[(c4 + 0) * SQS + r] = v.x;
        Qs[(c4 + 1) * SQS + r] = v.y;
        Qs[(c4 + 2) * SQS + r] = v.z;
        Qs[(c4 + 3) * SQS + r] = v.w;
    }

    float m_i[4], l_i[4], o[4][8];
#pragma unroll
    for (int i = 0; i < 4; ++i) {
        m_i[i] = -1e30f; l_i[i] = 0.f;
#pragma unroll
        for (int c = 0; c < 8; ++c) o[i][c] = 0.f;
    }

    for (int ktile = 0; ktile < SKV / KT; ++ktile) {
        const int kv0 = ktile * KT;
        __syncthreads();   // previous PV done before overwriting K/V (also covers Q load 1st iter)

        // ---- load K (transposed), V (row-major), mask ----
        for (int e = tid; e < KT * 32; e += 256) {
            int r = e >> 5, c4 = (e & 31) << 2;
            int jg = kv0 + r;
            const float *ksrc, *vsrc;
            if (jg < PAST) {
                size_t base = ((size_t)(b * NKV + hkv) * PAST + jg) * HD + c4;
                ksrc = pastk + base; vsrc = pastv + base;
            } else {
                size_t base = (size_t)(b * QL + (jg - PAST)) * (NKV * HD) + hkv * HD + c4;
                ksrc = g_k + base; vsrc = g_v + base;
            }
            float4 kk = *(const float4*)ksrc;
            Ks[(c4 + 0) * SQS + r] = kk.x;
            Ks[(c4 + 1) * SQS + r] = kk.y;
            Ks[(c4 + 2) * SQS + r] = kk.z;
            Ks[(c4 + 3) * SQS + r] = kk.w;
            *(float4*)&Vs[r * SVS + c4] = *(const float4*)vsrc;
        }
        if (tid < KT)
            Ms[tid] = (mask[b * SKV + kv0 + tid] == 0) ? 0.0f : -1e9f;
        __syncthreads();

        // ---- S = Q K^T (64x64) ----
        float s[4][4];
#pragma unroll
        for (int i = 0; i < 4; ++i)
#pragma unroll
            for (int j = 0; j < 4; ++j) s[i][j] = 0.f;

#pragma unroll 8
        for (int d = 0; d < HD; ++d) {
            float4 qa = *(const float4*)&Qs[d * SQS + ty4];
            float4 ka = *(const float4*)&Ks[d * SQS + tx4];
            float qv[4] = {qa.x, qa.y, qa.z, qa.w};
            float kv[4] = {ka.x, ka.y, ka.z, ka.w};
#pragma unroll
            for (int i = 0; i < 4; ++i)
#pragma unroll
                for (int j = 0; j < 4; ++j) s[i][j] += qv[i] * kv[j];
        }
        float mk0 = Ms[tx4], mk1 = Ms[tx4 + 1], mk2 = Ms[tx4 + 2], mk3 = Ms[tx4 + 3];
#pragma unroll
        for (int i = 0; i < 4; ++i) {
            s[i][0] += mk0; s[i][1] += mk1; s[i][2] += mk2; s[i][3] += mk3;
        }

        // ---- online softmax (row groups shared by 16 lanes of a half-warp) ----
#pragma unroll
        for (int i = 0; i < 4; ++i) {
            float rmax = fmaxf(fmaxf(s[i][0], s[i][1]), fmaxf(s[i][2], s[i][3]));
#pragma unroll
            for (int off = 8; off; off >>= 1)
                rmax = fmaxf(rmax, __shfl_xor_sync(0xffffffffu, rmax, off));
            float mn = fmaxf(m_i[i], rmax);
            float corr = __expf(m_i[i] - mn);
            float p0 = __expf(s[i][0] - mn);
            float p1 = __expf(s[i][1] - mn);
            float p2 = __expf(s[i][2] - mn);
            float p3 = __expf(s[i][3] - mn);
            float rs = (p0 + p1) + (p2 + p3);
#pragma unroll
            for (int off = 8; off; off >>= 1)
                rs += __shfl_xor_sync(0xffffffffu, rs, off);
            l_i[i] = l_i[i] * corr + rs;
            m_i[i] = mn;
#pragma unroll
            for (int c = 0; c < 8; ++c) o[i][c] *= corr;
            Pt[(tx4 + 0) * SQS + ty4 + i] = p0;
            Pt[(tx4 + 1) * SQS + ty4 + i] = p1;
            Pt[(tx4 + 2) * SQS + ty4 + i] = p2;
            Pt[(tx4 + 3) * SQS + ty4 + i] = p3;
        }
        __syncthreads();

        // ---- O += P V ----
#pragma unroll 4
        for (int j = 0; j < KT; ++j) {
            float4 p4 = *(const float4*)&Pt[j * SQS + ty4];
            float4 va = *(const float4*)&Vs[j * SVS + tx4];
            float4 vb = *(const float4*)&Vs[j * SVS + 64 + tx4];
            float pv[4] = {p4.x, p4.y, p4.z, p4.w};
            float vv[8] = {va.x, va.y, va.z, va.w, vb.x, vb.y, vb.z, vb.w};
#pragma unroll
            for (int i = 0; i < 4; ++i)
#pragma unroll
                for (int c = 0; c < 8; ++c) o[i][c] += pv[i] * vv[c];
        }
    }

    // ---- epilogue: normalize and write [B*Sq, H*D] ----
#pragma unroll
    for (int i = 0; i < 4; ++i) {
        float inv = 1.0f / l_i[i];
        size_t row = (size_t)(b * QL + q0 + ty4 + i);
        float4 r0 = {o[i][0] * inv, o[i][1] * inv, o[i][2] * inv, o[i][3] * inv};
        float4 r1 = {o[i][4] * inv, o[i][5] * inv, o[i][6] * inv, o[i][7] * inv};
        *(float4*)&g_att[row * HIDN + h * HD + tx4]      = r0;
        *(float4*)&g_att[row * HIDN + h * HD + 64 + tx4] = r1;
    }
}

// ======================================================================
extern "C" void kernel_launch(void* const* d_in, const int* in_sizes, int n_in,
                              void* d_out, int out_size)
{
    (void)in_sizes; (void)n_in; (void)out_size;
    const float* hidden = (const float*)d_in[0];
    const float* pastk  = (const float*)d_in[1];
    const float* pastv  = (const float*)d_in[2];
    const int*   mask   = (const int*)  d_in[3];
    const float* Wq = (const float*)d_in[4];
    const float* bq = (const float*)d_in[5];
    const float* Wk = (const float*)d_in[6];
    const float* bk = (const float*)d_in[7];
    const float* Wv = (const float*)d_in[8];
    const float* bv = (const float*)d_in[9];
    const float* Wo = (const float*)d_in[10];
    const float* bo = (const float*)d_in[11];
    float* out = (float*)d_out;

    float *qp, *kp, *vp, *ap;
    cudaGetSymbolAddress((void**)&qp, g_q);
    cudaGetSymbolAddress((void**)&kp, g_k);
    cudaGetSymbolAddress((void**)&vp, g_v);
    cudaGetSymbolAddress((void**)&ap, g_att);

    cudaFuncSetAttribute(attn_kernel, cudaFuncAttributeMaxDynamicSharedMemorySize,
                         ATTN_SMEM_BYTES);

    const float alpha_q = 0.08838834764831845f;  // SCALING * 1/sqrt(HEAD_DIM)
    dim3 blk(256);

    // QKV projections
    gemm_nt<<<dim3(32, 32), blk>>>(hidden, Wq, bq, qp, MROWS, HIDN, HIDN, alpha_q);
    gemm_nt<<<dim3(8, 32),  blk>>>(hidden, Wk, bk, kp, MROWS, NKV * HD, HIDN, 1.0f);
    gemm_nt<<<dim3(8, 32),  blk>>>(hidden, Wv, bv, vp, MROWS, NKV * HD, HIDN, 1.0f);

    // attention
    attn_kernel<<<dim3(QL / QT, NH, BB), blk, ATTN_SMEM_BYTES>>>(pastk, pastv, mask);

    // output projection
    gemm_nt<<<dim3(32, 32), blk>>>(ap, Wo, bo, out, MROWS, HIDN, HIDN, 1.0f);
}

// round 5
// speedup vs baseline: 2.3563x; 2.3563x over previous
#include <cuda_runtime.h>
#include <cstdint>
#include <math.h>

#define HIDN 4096
#define NH   32
#define NKV  8
#define HD   128
#define BB   4
#define QL   1024
#define PAST 1024
#define SKV  2048
#define MROWS (BB*QL)   /* 4096 */

// -------- scratch (device globals; no allocation allowed) --------
__device__ float g_q[(size_t)MROWS * HIDN];        // [B*Sq, H*D]
__device__ float g_k[(size_t)MROWS * (NKV * HD)];  // [B*Sq, Hkv*D]
__device__ float g_v[(size_t)MROWS * (NKV * HD)];
__device__ float g_att[(size_t)MROWS * HIDN];      // [B*Sq, H*D]

// ======================================================================
// helpers
// ======================================================================
__device__ __forceinline__ uint32_t smem_u32(const void* p) {
    uint32_t a;
    asm("{ .reg .u64 t; cvta.to.shared.u64 t, %1; cvt.u32.u64 %0, t; }" : "=r"(a) : "l"(p));
    return a;
}

__device__ __forceinline__ void cp_async16(uint32_t s, const void* g) {
    asm volatile("cp.async.cg.shared.global [%0], [%1], 16;" :: "r"(s), "l"(g) : "memory");
}

__device__ __forceinline__ uint32_t f2tf32(float x) {
    uint32_t r;
    asm("cvt.rna.tf32.f32 %0, %1;" : "=r"(r) : "f"(x));
    return r;
}

__device__ __forceinline__ void mma_tf32_16n8k8(float* c, const uint32_t* a, const uint32_t* b) {
    asm volatile(
        "mma.sync.aligned.m16n8k8.row.col.f32.tf32.tf32.f32 "
        "{%0,%1,%2,%3}, {%4,%5,%6,%7}, {%8,%9}, {%0,%1,%2,%3};"
        : "+f"(c[0]), "+f"(c[1]), "+f"(c[2]), "+f"(c[3])
        : "r"(a[0]), "r"(a[1]), "r"(a[2]), "r"(a[3]), "r"(b[0]), "r"(b[1]));
}

// ======================================================================
// tf32 mma.sync GEMM-NT: C[m,n] = alpha * ( sum_k A[m,k]*W[n,k] + bias[n] )
// A: [M,K] row-major, W: [N,K] row-major (both K-major -> mma row.col).
// CTA tile 128x128, BK=16, 8 warps of 64x32, double-buffered cp.async.
// ======================================================================
#define SA 20   /* smem row stride (floats): conflict-free for frag loads */

__global__ __launch_bounds__(256) void gemm_mma(
    const float* __restrict__ A, const float* __restrict__ W,
    const float* __restrict__ bias, float* __restrict__ C,
    int ldc, int K, float alpha)
{
    __shared__ float As[2][128][SA];
    __shared__ float Bs[2][128][SA];

    const int tid  = threadIdx.x;
    const int lane = tid & 31, w = tid >> 5;
    const int g = lane >> 2, t = lane & 3;
    const int wm = (w & 1) * 64, wn = (w >> 1) * 32;
    const int bm = blockIdx.y * 128, bn = blockIdx.x * 128;

    const int r  = tid >> 2;          // loader row 0..63
    const int c4 = (tid & 3) << 2;    // loader col 0,4,8,12

    const float* aBase = A + (size_t)(bm + r) * K + c4;
    const float* bBase = W + (size_t)(bn + r) * K + c4;
    const size_t rowskip = (size_t)64 * K;

    float acc[4][4][4];
#pragma unroll
    for (int mi = 0; mi < 4; ++mi)
#pragma unroll
        for (int ni = 0; ni < 4; ++ni)
#pragma unroll
            for (int e = 0; e < 4; ++e) acc[mi][ni][e] = 0.f;

    const int kiters = K >> 4;

    // prologue: stage 0
    {
        const float* ag = aBase;
        const float* bg = bBase;
        cp_async16(smem_u32(&As[0][r][c4]), ag);
        cp_async16(smem_u32(&As[0][r + 64][c4]), ag + rowskip);
        cp_async16(smem_u32(&Bs[0][r][c4]), bg);
        cp_async16(smem_u32(&Bs[0][r + 64][c4]), bg + rowskip);
        asm volatile("cp.async.commit_group;" ::: "memory");
    }

    for (int it = 0; it < kiters; ++it) {
        const int buf = it & 1;
        if (it + 1 < kiters) {
            const float* ag = aBase + (size_t)(it + 1) * 16;
            const float* bg = bBase + (size_t)(it + 1) * 16;
            cp_async16(smem_u32(&As[buf ^ 1][r][c4]), ag);
            cp_async16(smem_u32(&As[buf ^ 1][r + 64][c4]), ag + rowskip);
            cp_async16(smem_u32(&Bs[buf ^ 1][r][c4]), bg);
            cp_async16(smem_u32(&Bs[buf ^ 1][r + 64][c4]), bg + rowskip);
            asm volatile("cp.async.commit_group;" ::: "memory");
            asm volatile("cp.async.wait_group 1;" ::: "memory");
        } else {
            asm volatile("cp.async.wait_group 0;" ::: "memory");
        }
        __syncthreads();

#pragma unroll
        for (int ks = 0; ks < 16; ks += 8) {
            uint32_t af[4][4], bf[4][2];
#pragma unroll
            for (int mi = 0; mi < 4; ++mi) {
                const int mr = wm + 16 * mi + g;
                af[mi][0] = f2tf32(As[buf][mr][ks + t]);
                af[mi][1] = f2tf32(As[buf][mr + 8][ks + t]);
                af[mi][2] = f2tf32(As[buf][mr][ks + t + 4]);
                af[mi][3] = f2tf32(As[buf][mr + 8][ks + t + 4]);
            }
#pragma unroll
            for (int ni = 0; ni < 4; ++ni) {
                const int nr = wn + 8 * ni + g;
                bf[ni][0] = f2tf32(Bs[buf][nr][ks + t]);
                bf[ni][1] = f2tf32(Bs[buf][nr][ks + t + 4]);
            }
#pragma unroll
            for (int mi = 0; mi < 4; ++mi)
#pragma unroll
                for (int ni = 0; ni < 4; ++ni)
                    mma_tf32_16n8k8(acc[mi][ni], af[mi], bf[ni]);
        }
        __syncthreads();
    }

    // epilogue
#pragma unroll
    for (int mi = 0; mi < 4; ++mi) {
        const int row0 = bm + wm + 16 * mi + g;
#pragma unroll
        for (int ni = 0; ni < 4; ++ni) {
            const int col = bn + wn + 8 * ni + 2 * t;
            const float b0 = bias[col], b1 = bias[col + 1];
            float2 v0, v1;
            v0.x = alpha * (acc[mi][ni][0] + b0);
            v0.y = alpha * (acc[mi][ni][1] + b1);
            v1.x = alpha * (acc[mi][ni][2] + b0);
            v1.y = alpha * (acc[mi][ni][3] + b1);
            *(float2*)&C[(size_t)row0 * ldc + col]       = v0;
            *(float2*)&C[(size_t)(row0 + 8) * ldc + col] = v1;
        }
    }
}

// ======================================================================
// Flash attention (fp32 SIMT, known-good from round 1)
// ======================================================================
#define QT 64
#define KT 64
#define SQS 68
#define SVS 132
#define ATTN_SMEM_FLOATS (128*SQS + 128*SQS + KT*SVS + KT*SQS)
#define ATTN_SMEM_BYTES (ATTN_SMEM_FLOATS * 4)

__global__ __launch_bounds__(256) void attn_kernel(
    const float* __restrict__ pastk, const float* __restrict__ pastv,
    const int* __restrict__ mask)
{
    extern __shared__ __align__(1024) float sm[];
    float* Qs = sm;
    float* Ks = Qs + 128 * SQS;
    float* Vs = Ks + 128 * SQS;
    float* Pt = Vs + KT * SVS;
    __shared__ float Ms[KT];

    const int tid = threadIdx.x;
    const int qt = blockIdx.x, h = blockIdx.y, b = blockIdx.z;
    const int hkv = h >> 2;
    const int q0 = qt * QT;

    const int ty4 = (tid >> 4) << 2;
    const int tx4 = (tid & 15) << 2;

    for (int e = tid; e < QT * 32; e += 256) {
        int r = e >> 5, c4 = (e & 31) << 2;
        const float4 v = *(const float4*)(g_q + (size_t)(b * QL + q0 + r) * HIDN + h * HD + c4);
        Qs[(c4 + 0) * SQS + r] = v.x;
        Qs[(c4 + 1) * SQS + r] = v.y;
        Qs[(c4 + 2) * SQS + r] = v.z;
        Qs[(c4 + 3) * SQS + r] = v.w;
    }

    float m_i[4], l_i[4], o[4][8];
#pragma unroll
    for (int i = 0; i < 4; ++i) {
        m_i[i] = -1e30f; l_i[i] = 0.f;
#pragma unroll
        for (int c = 0; c < 8; ++c) o[i][c] = 0.f;
    }

    for (int ktile = 0; ktile < SKV / KT; ++ktile) {
        const int kv0 = ktile * KT;
        __syncthreads();

        for (int e = tid; e < KT * 32; e += 256) {
            int r = e >> 5, c4 = (e & 31) << 2;
            int jg = kv0 + r;
            const float *ksrc, *vsrc;
            if (jg < PAST) {
                size_t base = ((size_t)(b * NKV + hkv) * PAST + jg) * HD + c4;
                ksrc = pastk + base; vsrc = pastv + base;
            } else {
                size_t base = (size_t)(b * QL + (jg - PAST)) * (NKV * HD) + hkv * HD + c4;
                ksrc = g_k + base; vsrc = g_v + base;
            }
            float4 kk = *(const float4*)ksrc;
            Ks[(c4 + 0) * SQS + r] = kk.x;
            Ks[(c4 + 1) * SQS + r] = kk.y;
            Ks[(c4 + 2) * SQS + r] = kk.z;
            Ks[(c4 + 3) * SQS + r] = kk.w;
            *(float4*)&Vs[r * SVS + c4] = *(const float4*)vsrc;
        }
        if (tid < KT)
            Ms[tid] = (mask[b * SKV + kv0 + tid] == 0) ? 0.0f : -1e9f;
        __syncthreads();

        float s[4][4];
#pragma unroll
        for (int i = 0; i < 4; ++i)
#pragma unroll
            for (int j = 0; j < 4; ++j) s[i][j] = 0.f;

#pragma unroll 8
        for (int d = 0; d < HD; ++d) {
            float4 qa = *(const float4*)&Qs[d * SQS + ty4];
            float4 ka = *(const float4*)&Ks[d * SQS + tx4];
            float qv[4] = {qa.x, qa.y, qa.z, qa.w};
            float kv[4] = {ka.x, ka.y, ka.z, ka.w};
#pragma unroll
            for (int i = 0; i < 4; ++i)
#pragma unroll
                for (int j = 0; j < 4; ++j) s[i][j] += qv[i] * kv[j];
        }
        float mk0 = Ms[tx4], mk1 = Ms[tx4 + 1], mk2 = Ms[tx4 + 2], mk3 = Ms[tx4 + 3];
#pragma unroll
        for (int i = 0; i < 4; ++i) {
            s[i][0] += mk0; s[i][1] += mk1; s[i][2] += mk2; s[i][3] += mk3;
        }

#pragma unroll
        for (int i = 0; i < 4; ++i) {
            float rmax = fmaxf(fmaxf(s[i][0], s[i][1]), fmaxf(s[i][2], s[i][3]));
#pragma unroll
            for (int off = 8; off; off >>= 1)
                rmax = fmaxf(rmax, __shfl_xor_sync(0xffffffffu, rmax, off));
            float mn = fmaxf(m_i[i], rmax);
            float corr = __expf(m_i[i] - mn);
            float p0 = __expf(s[i][0] - mn);
            float p1 = __expf(s[i][1] - mn);
            float p2 = __expf(s[i][2] - mn);
            float p3 = __expf(s[i][3] - mn);
            float rs = (p0 + p1) + (p2 + p3);
#pragma unroll
            for (int off = 8; off; off >>= 1)
                rs += __shfl_xor_sync(0xffffffffu, rs, off);
            l_i[i] = l_i[i] * corr + rs;
            m_i[i] = mn;
#pragma unroll
            for (int c = 0; c < 8; ++c) o[i][c] *= corr;
            Pt[(tx4 + 0) * SQS + ty4 + i] = p0;
            Pt[(tx4 + 1) * SQS + ty4 + i] = p1;
            Pt[(tx4 + 2) * SQS + ty4 + i] = p2;
            Pt[(tx4 + 3) * SQS + ty4 + i] = p3;
        }
        __syncthreads();

#pragma unroll 4
        for (int j = 0; j < KT; ++j) {
            float4 p4 = *(const float4*)&Pt[j * SQS + ty4];
            float4 va = *(const float4*)&Vs[j * SVS + tx4];
            float4 vb = *(const float4*)&Vs[j * SVS + 64 + tx4];
            float pv[4] = {p4.x, p4.y, p4.z, p4.w};
            float vv[8] = {va.x, va.y, va.z, va.w, vb.x, vb.y, vb.z, vb.w};
#pragma unroll
            for (int i = 0; i < 4; ++i)
#pragma unroll
                for (int c = 0; c < 8; ++c) o[i][c] += pv[i] * vv[c];
        }
    }

#pragma unroll
    for (int i = 0; i < 4; ++i) {
        float inv = 1.0f / l_i[i];
        size_t row = (size_t)(b * QL + q0 + ty4 + i);
        float4 r0 = {o[i][0] * inv, o[i][1] * inv, o[i][2] * inv, o[i][3] * inv};
        float4 r1 = {o[i][4] * inv, o[i][5] * inv, o[i][6] * inv, o[i][7] * inv};
        *(float4*)&g_att[row * HIDN + h * HD + tx4]      = r0;
        *(float4*)&g_att[row * HIDN + h * HD + 64 + tx4] = r1;
    }
}

// ======================================================================
extern "C" void kernel_launch(void* const* d_in, const int* in_sizes, int n_in,
                              void* d_out, int out_size)
{
    (void)in_sizes; (void)n_in; (void)out_size;
    const float* hidden = (const float*)d_in[0];
    const float* pastk  = (const float*)d_in[1];
    const float* pastv  = (const float*)d_in[2];
    const int*   mask   = (const int*)  d_in[3];
    const float* Wq = (const float*)d_in[4];
    const float* bq = (const float*)d_in[5];
    const float* Wk = (const float*)d_in[6];
    const float* bk = (const float*)d_in[7];
    const float* Wv = (const float*)d_in[8];
    const float* bv = (const float*)d_in[9];
    const float* Wo = (const float*)d_in[10];
    const float* bo = (const float*)d_in[11];
    float* out = (float*)d_out;

    float *qp, *kp, *vp, *ap;
    cudaGetSymbolAddress((void**)&qp, g_q);
    cudaGetSymbolAddress((void**)&kp, g_k);
    cudaGetSymbolAddress((void**)&vp, g_v);
    cudaGetSymbolAddress((void**)&ap, g_att);

    cudaFuncSetAttribute(attn_kernel, cudaFuncAttributeMaxDynamicSharedMemorySize,
                         ATTN_SMEM_BYTES);

    const float alpha_q = 0.08838834764831845f;  // SCALING / sqrt(HEAD_DIM)
    dim3 blk(256);

    // QKV projections (tf32 tensor cores)
    gemm_mma<<<dim3(HIDN / 128, MROWS / 128), blk>>>(hidden, Wq, bq, qp, HIDN, HIDN, alpha_q);
    gemm_mma<<<dim3((NKV * HD) / 128, MROWS / 128), blk>>>(hidden, Wk, bk, kp, NKV * HD, HIDN, 1.0f);
    gemm_mma<<<dim3((NKV * HD) / 128, MROWS / 128), blk>>>(hidden, Wv, bv, vp, NKV * HD, HIDN, 1.0f);

    // attention
    attn_kernel<<<dim3(QL / QT, NH, BB), blk, ATTN_SMEM_BYTES>>>(pastk, pastv, mask);

    // output projection
    gemm_mma<<<dim3(HIDN / 128, MROWS / 128), blk>>>(ap, Wo, bo, out, HIDN, HIDN, 1.0f);
}

// round 7
// speedup vs baseline: 4.1533x; 1.7626x over previous
#include <cuda_runtime.h>
#include <cstdint>
#include <math.h>

#define HIDN 4096
#define NH   32
#define NKV  8
#define HD   128
#define BB   4
#define QL   1024
#define PAST 1024
#define SKV  2048
#define MROWS (BB*QL)   /* 4096 */

// -------- scratch (device globals; no allocation allowed) --------
__device__ float g_q[(size_t)MROWS * HIDN];        // [B*Sq, H*D] (tf32-rounded q * alpha)
__device__ float g_k[(size_t)MROWS * (NKV * HD)];  // [B*Sq, Hkv*D]
__device__ float g_v[(size_t)MROWS * (NKV * HD)];
__device__ float g_att[(size_t)MROWS * HIDN];      // [B*Sq, H*D]

// ======================================================================
// helpers
// ======================================================================
__device__ __forceinline__ uint32_t smem_u32(const void* p) {
    uint32_t a;
    asm("{ .reg .u64 t; cvta.to.shared.u64 t, %1; cvt.u32.u64 %0, t; }" : "=r"(a) : "l"(p));
    return a;
}

__device__ __forceinline__ void cp_async16(uint32_t s, const void* g) {
    asm volatile("cp.async.cg.shared.global [%0], [%1], 16;" :: "r"(s), "l"(g) : "memory");
}

__device__ __forceinline__ uint32_t f2tf32(float x) {
    uint32_t r;
    asm("cvt.rna.tf32.f32 %0, %1;" : "=r"(r) : "f"(x));
    return r;
}
__device__ __forceinline__ float f2tf32f(float x) { return __uint_as_float(f2tf32(x)); }

__device__ __forceinline__ void mma_tf32_16n8k8(float* c, const uint32_t* a, const uint32_t* b) {
    asm volatile(
        "mma.sync.aligned.m16n8k8.row.col.f32.tf32.tf32.f32 "
        "{%0,%1,%2,%3}, {%4,%5,%6,%7}, {%8,%9}, {%0,%1,%2,%3};"
        : "+f"(c[0]), "+f"(c[1]), "+f"(c[2]), "+f"(c[3])
        : "r"(a[0]), "r"(a[1]), "r"(a[2]), "r"(a[3]), "r"(b[0]), "r"(b[1]));
}

// ======================================================================
// tf32 mma.sync GEMM-NT (unchanged, passing): C = alpha*(A W^T + bias)
// ======================================================================
#define SA 20

__global__ __launch_bounds__(256) void gemm_mma(
    const float* __restrict__ A, const float* __restrict__ W,
    const float* __restrict__ bias, float* __restrict__ C,
    int ldc, int K, float alpha)
{
    __shared__ float As[2][128][SA];
    __shared__ float Bs[2][128][SA];

    const int tid  = threadIdx.x;
    const int lane = tid & 31, w = tid >> 5;
    const int g = lane >> 2, t = lane & 3;
    const int wm = (w & 1) * 64, wn = (w >> 1) * 32;
    const int bm = blockIdx.y * 128, bn = blockIdx.x * 128;

    const int r  = tid >> 2;
    const int c4 = (tid & 3) << 2;

    const float* aBase = A + (size_t)(bm + r) * K + c4;
    const float* bBase = W + (size_t)(bn + r) * K + c4;
    const size_t rowskip = (size_t)64 * K;

    float acc[4][4][4];
#pragma unroll
    for (int mi = 0; mi < 4; ++mi)
#pragma unroll
        for (int ni = 0; ni < 4; ++ni)
#pragma unroll
            for (int e = 0; e < 4; ++e) acc[mi][ni][e] = 0.f;

    const int kiters = K >> 4;

    {
        cp_async16(smem_u32(&As[0][r][c4]), aBase);
        cp_async16(smem_u32(&As[0][r + 64][c4]), aBase + rowskip);
        cp_async16(smem_u32(&Bs[0][r][c4]), bBase);
        cp_async16(smem_u32(&Bs[0][r + 64][c4]), bBase + rowskip);
        asm volatile("cp.async.commit_group;" ::: "memory");
    }

    for (int it = 0; it < kiters; ++it) {
        const int buf = it & 1;
        if (it + 1 < kiters) {
            const float* ag = aBase + (size_t)(it + 1) * 16;
            const float* bg = bBase + (size_t)(it + 1) * 16;
            cp_async16(smem_u32(&As[buf ^ 1][r][c4]), ag);
            cp_async16(smem_u32(&As[buf ^ 1][r + 64][c4]), ag + rowskip);
            cp_async16(smem_u32(&Bs[buf ^ 1][r][c4]), bg);
            cp_async16(smem_u32(&Bs[buf ^ 1][r + 64][c4]), bg + rowskip);
            asm volatile("cp.async.commit_group;" ::: "memory");
            asm volatile("cp.async.wait_group 1;" ::: "memory");
        } else {
            asm volatile("cp.async.wait_group 0;" ::: "memory");
        }
        __syncthreads();

#pragma unroll
        for (int ks = 0; ks < 16; ks += 8) {
            uint32_t af[4][4], bf[4][2];
#pragma unroll
            for (int mi = 0; mi < 4; ++mi) {
                const int mr = wm + 16 * mi + g;
                af[mi][0] = f2tf32(As[buf][mr][ks + t]);
                af[mi][1] = f2tf32(As[buf][mr + 8][ks + t]);
                af[mi][2] = f2tf32(As[buf][mr][ks + t + 4]);
                af[mi][3] = f2tf32(As[buf][mr + 8][ks + t + 4]);
            }
#pragma unroll
            for (int ni = 0; ni < 4; ++ni) {
                const int nr = wn + 8 * ni + g;
                bf[ni][0] = f2tf32(Bs[buf][nr][ks + t]);
                bf[ni][1] = f2tf32(Bs[buf][nr][ks + t + 4]);
            }
#pragma unroll
            for (int mi = 0; mi < 4; ++mi)
#pragma unroll
                for (int ni = 0; ni < 4; ++ni)
                    mma_tf32_16n8k8(acc[mi][ni], af[mi], bf[ni]);
        }
        __syncthreads();
    }

#pragma unroll
    for (int mi = 0; mi < 4; ++mi) {
        const int row0 = bm + wm + 16 * mi + g;
#pragma unroll
        for (int ni = 0; ni < 4; ++ni) {
            const int col = bn + wn + 8 * ni + 2 * t;
            const float b0 = bias[col], b1 = bias[col + 1];
            float2 v0, v1;
            v0.x = alpha * (acc[mi][ni][0] + b0);
            v0.y = alpha * (acc[mi][ni][1] + b1);
            v1.x = alpha * (acc[mi][ni][2] + b0);
            v1.y = alpha * (acc[mi][ni][3] + b1);
            *(float2*)&C[(size_t)row0 * ldc + col]       = v0;
            *(float2*)&C[(size_t)(row0 + 8) * ldc + col] = v1;
        }
    }
}

// ======================================================================
// Tensor-core flash attention (tf32 mma.sync)
// CTA: 128 q-rows x (b,h). KV tile 64. 8 warps, warp w owns rows [16w,16w+16).
// smem operands stored pre-converted to tf32 bit patterns.
// ======================================================================
#define SQ 132   /* row stride for Qs/Ks/Vs */
#define SP 68    /* row stride for Ps */
#define ATTN2_FLOATS (128*SQ + 64*SQ + 64*SQ + 128*SP + 64)
#define ATTN2_SMEM (ATTN2_FLOATS * 4)

__global__ __launch_bounds__(256, 1) void attn_mma(
    const float* __restrict__ pastk, const float* __restrict__ pastv,
    const int* __restrict__ mask)
{
    extern __shared__ __align__(16) float sm[];
    float* Qs = sm;                 // [128][SQ]
    float* Ks = Qs + 128 * SQ;      // [64][SQ]
    float* Vs = Ks + 64 * SQ;       // [64][SQ]
    float* Ps = Vs + 64 * SQ;       // [128][SP]
    float* Ms = Ps + 128 * SP;      // [64]

    const int tid = threadIdx.x;
    const int lane = tid & 31, w = tid >> 5;
    const int g = lane >> 2, t = lane & 3;
    const int c2 = 2 * t;
    const int qt = blockIdx.x, h = blockIdx.y, b = blockIdx.z;
    const int hkv = h >> 2;
    const int q0 = qt * 128;

    // ---- load Q tile, convert to tf32 ----
    for (int e = tid; e < 128 * 32; e += 256) {
        int r = e >> 5, c4 = (e & 31) << 2;
        float4 v = *(const float4*)(g_q + (size_t)(b * QL + q0 + r) * HIDN + h * HD + c4);
        float4 o = {f2tf32f(v.x), f2tf32f(v.y), f2tf32f(v.z), f2tf32f(v.w)};
        *(float4*)&Qs[r * SQ + c4] = o;
    }

    float m0 = -1e30f, m1 = -1e30f, l0 = 0.f, l1 = 0.f;
    float o_[16][4];
#pragma unroll
    for (int nt = 0; nt < 16; ++nt)
#pragma unroll
        for (int e = 0; e < 4; ++e) o_[nt][e] = 0.f;

    const uint32_t* Qu = (const uint32_t*)Qs;
    const uint32_t* Ku = (const uint32_t*)Ks;
    const uint32_t* Vu = (const uint32_t*)Vs;
    const uint32_t* Pu = (const uint32_t*)Ps;

    const int rA0 = (16 * w + g) * SQ;
    const int rA1 = (16 * w + g + 8) * SQ;
    const int pA0 = (16 * w + g) * SP;
    const int pA1 = (16 * w + g + 8) * SP;

    for (int kt = 0; kt < SKV / 64; ++kt) {
        const int kv0 = kt * 64;
        __syncthreads();   // K/V consumers of previous tile done (also covers Q stores, 1st iter)

        // ---- load K/V tile, convert to tf32 ----
        for (int e = tid; e < 64 * 32; e += 256) {
            int r = e >> 5, c4 = (e & 31) << 2;
            int jg = kv0 + r;
            const float *ksrc, *vsrc;
            if (jg < PAST) {
                size_t base = ((size_t)(b * NKV + hkv) * PAST + jg) * HD + c4;
                ksrc = pastk + base; vsrc = pastv + base;
            } else {
                size_t base = (size_t)(b * QL + (jg - PAST)) * (NKV * HD) + hkv * HD + c4;
                ksrc = g_k + base; vsrc = g_v + base;
            }
            float4 kk = *(const float4*)ksrc;
            float4 vv = *(const float4*)vsrc;
            float4 ko = {f2tf32f(kk.x), f2tf32f(kk.y), f2tf32f(kk.z), f2tf32f(kk.w)};
            float4 vo = {f2tf32f(vv.x), f2tf32f(vv.y), f2tf32f(vv.z), f2tf32f(vv.w)};
            *(float4*)&Ks[r * SQ + c4] = ko;
            *(float4*)&Vs[r * SQ + c4] = vo;
        }
        if (tid < 64)
            Ms[tid] = (mask[b * SKV + kv0 + tid] == 0) ? 0.0f : -1e9f;
        __syncthreads();

        // ---- S = Q K^T  (warp: 16 x 64) ----
        float s[8][4];
#pragma unroll
        for (int nt = 0; nt < 8; ++nt)
#pragma unroll
            for (int e = 0; e < 4; ++e) s[nt][e] = 0.f;

#pragma unroll
        for (int ks = 0; ks < 128; ks += 8) {
            uint32_t a[4] = {Qu[rA0 + ks + t], Qu[rA1 + ks + t],
                             Qu[rA0 + ks + t + 4], Qu[rA1 + ks + t + 4]};
#pragma unroll
            for (int nt = 0; nt < 8; ++nt) {
                uint32_t bb[2] = {Ku[(nt * 8 + g) * SQ + ks + t],
                                  Ku[(nt * 8 + g) * SQ + ks + t + 4]};
                mma_tf32_16n8k8(s[nt], a, bb);
            }
        }

        // ---- mask + online softmax ----
        float rm0 = -1e30f, rm1 = -1e30f;
#pragma unroll
        for (int nt = 0; nt < 8; ++nt) {
            float mk0 = Ms[nt * 8 + c2], mk1 = Ms[nt * 8 + c2 + 1];
            s[nt][0] += mk0; s[nt][1] += mk1;
            s[nt][2] += mk0; s[nt][3] += mk1;
            rm0 = fmaxf(rm0, fmaxf(s[nt][0], s[nt][1]));
            rm1 = fmaxf(rm1, fmaxf(s[nt][2], s[nt][3]));
        }
        rm0 = fmaxf(rm0, __shfl_xor_sync(0xffffffffu, rm0, 1));
        rm0 = fmaxf(rm0, __shfl_xor_sync(0xffffffffu, rm0, 2));
        rm1 = fmaxf(rm1, __shfl_xor_sync(0xffffffffu, rm1, 1));
        rm1 = fmaxf(rm1, __shfl_xor_sync(0xffffffffu, rm1, 2));

        float mn0 = fmaxf(m0, rm0), mn1 = fmaxf(m1, rm1);
        float corr0 = __expf(m0 - mn0), corr1 = __expf(m1 - mn1);
        float rs0 = 0.f, rs1 = 0.f;
#pragma unroll
        for (int nt = 0; nt < 8; ++nt) {
            float p0 = __expf(s[nt][0] - mn0);
            float p1 = __expf(s[nt][1] - mn0);
            float p2 = __expf(s[nt][2] - mn1);
            float p3 = __expf(s[nt][3] - mn1);
            rs0 += p0 + p1; rs1 += p2 + p3;
            Ps[pA0 + nt * 8 + c2]     = f2tf32f(p0);
            Ps[pA0 + nt * 8 + c2 + 1] = f2tf32f(p1);
            Ps[pA1 + nt * 8 + c2]     = f2tf32f(p2);
            Ps[pA1 + nt * 8 + c2 + 1] = f2tf32f(p3);
        }
        rs0 += __shfl_xor_sync(0xffffffffu, rs0, 1);
        rs0 += __shfl_xor_sync(0xffffffffu, rs0, 2);
        rs1 += __shfl_xor_sync(0xffffffffu, rs1, 1);
        rs1 += __shfl_xor_sync(0xffffffffu, rs1, 2);

        l0 = l0 * corr0 + rs0; m0 = mn0;
        l1 = l1 * corr1 + rs1; m1 = mn1;
#pragma unroll
        for (int nt = 0; nt < 16; ++nt) {
            o_[nt][0] *= corr0; o_[nt][1] *= corr0;
            o_[nt][2] *= corr1; o_[nt][3] *= corr1;
        }
        __syncwarp();   // P stripe visible to own warp's lanes

        // ---- O += P V  (warp: 16 x 128, k = 64) ----
#pragma unroll
        for (int ks = 0; ks < 64; ks += 8) {
            uint32_t a[4] = {Pu[pA0 + ks + t], Pu[pA1 + ks + t],
                             Pu[pA0 + ks + t + 4], Pu[pA1 + ks + t + 4]};
#pragma unroll
            for (int nt = 0; nt < 16; ++nt) {
                uint32_t bb[2] = {Vu[(ks + t) * SQ + nt * 8 + g],
                                  Vu[(ks + t + 4) * SQ + nt * 8 + g]};
                mma_tf32_16n8k8(o_[nt], a, bb);
            }
        }
    }

    // ---- epilogue ----
    float i0 = 1.0f / l0, i1 = 1.0f / l1;
    size_t row0 = (size_t)(b * QL + q0 + 16 * w + g);
    size_t row1 = row0 + 8;
#pragma unroll
    for (int nt = 0; nt < 16; ++nt) {
        int col = h * HD + nt * 8 + c2;
        float2 v0 = {o_[nt][0] * i0, o_[nt][1] * i0};
        float2 v1 = {o_[nt][2] * i1, o_[nt][3] * i1};
        *(float2*)&g_att[row0 * HIDN + col] = v0;
        *(float2*)&g_att[row1 * HIDN + col] = v1;
    }
}

// ======================================================================
extern "C" void kernel_launch(void* const* d_in, const int* in_sizes, int n_in,
                              void* d_out, int out_size)
{
    (void)in_sizes; (void)n_in; (void)out_size;
    const float* hidden = (const float*)d_in[0];
    const float* pastk  = (const float*)d_in[1];
    const float* pastv  = (const float*)d_in[2];
    const int*   mask   = (const int*)  d_in[3];
    const float* Wq = (const float*)d_in[4];
    const float* bq = (const float*)d_in[5];
    const float* Wk = (const float*)d_in[6];
    const float* bk = (const float*)d_in[7];
    const float* Wv = (const float*)d_in[8];
    const float* bv = (const float*)d_in[9];
    const float* Wo = (const float*)d_in[10];
    const float* bo = (const float*)d_in[11];
    float* out = (float*)d_out;

    float *qp, *kp, *vp, *ap;
    cudaGetSymbolAddress((void**)&qp, g_q);
    cudaGetSymbolAddress((void**)&kp, g_k);
    cudaGetSymbolAddress((void**)&vp, g_v);
    cudaGetSymbolAddress((void**)&ap, g_att);

    cudaFuncSetAttribute(attn_mma, cudaFuncAttributeMaxDynamicSharedMemorySize,
                         ATTN2_SMEM);

    const float alpha_q = 0.08838834764831845f;  // SCALING / sqrt(HEAD_DIM)
    dim3 blk(256);

    // QKV projections (tf32 tensor cores)
    gemm_mma<<<dim3(HIDN / 128, MROWS / 128), blk>>>(hidden, Wq, bq, qp, HIDN, HIDN, alpha_q);
    gemm_mma<<<dim3((NKV * HD) / 128, MROWS / 128), blk>>>(hidden, Wk, bk, kp, NKV * HD, HIDN, 1.0f);
    gemm_mma<<<dim3((NKV * HD) / 128, MROWS / 128), blk>>>(hidden, Wv, bv, vp, NKV * HD, HIDN, 1.0f);

    // attention (tf32 tensor cores)
    attn_mma<<<dim3(QL / 128, NH, BB), blk, ATTN2_SMEM>>>(pastk, pastv, mask);

    // output projection
    gemm_mma<<<dim3(HIDN / 128, MROWS / 128), blk>>>(ap, Wo, bo, out, HIDN, HIDN, 1.0f);
}

// round 10
// speedup vs baseline: 4.1877x; 1.0083x over previous
#include <cuda_runtime.h>
#include <cstdint>
#include <math.h>

#define HIDN 4096
#define NH   32
#define NKV  8
#define HD   128
#define BB   4
#define QL   1024
#define PAST 1024
#define SKV  2048
#define MROWS (BB*QL)   /* 4096 */

// -------- scratch (device globals; no allocation allowed) --------
__device__ float g_q[(size_t)MROWS * HIDN];        // [B*Sq, H*D]
__device__ float g_k[(size_t)MROWS * (NKV * HD)];  // [B*Sq, Hkv*D]
__device__ float g_v[(size_t)MROWS * (NKV * HD)];
__device__ float g_att[(size_t)MROWS * HIDN];      // [B*Sq, H*D]

// ======================================================================
// helpers
// ======================================================================
__device__ __forceinline__ uint32_t smem_u32(const void* p) {
    uint32_t a;
    asm("{ .reg .u64 t; cvta.to.shared.u64 t, %1; cvt.u32.u64 %0, t; }" : "=r"(a) : "l"(p));
    return a;
}

__device__ __forceinline__ void cp_async16(uint32_t s, const void* g) {
    asm volatile("cp.async.cg.shared.global [%0], [%1], 16;" :: "r"(s), "l"(g) : "memory");
}

__device__ __forceinline__ uint32_t f2tf32(float x) {
    uint32_t r;
    asm("cvt.rna.tf32.f32 %0, %1;" : "=r"(r) : "f"(x));
    return r;
}
__device__ __forceinline__ float f2tf32f(float x) { return __uint_as_float(f2tf32(x)); }

__device__ __forceinline__ void mma_tf32_16n8k8(float* c, const uint32_t* a, const uint32_t* b) {
    asm volatile(
        "mma.sync.aligned.m16n8k8.row.col.f32.tf32.tf32.f32 "
        "{%0,%1,%2,%3}, {%4,%5,%6,%7}, {%8,%9}, {%0,%1,%2,%3};"
        : "+f"(c[0]), "+f"(c[1]), "+f"(c[2]), "+f"(c[3])
        : "r"(a[0]), "r"(a[1]), "r"(a[2]), "r"(a[3]), "r"(b[0]), "r"(b[1]));
}

// ======================================================================
// tf32 mma.sync GEMM-NT: C[m,n] = alpha*( sum_k A[m,k]*W[n,k] + bias[n] )
// CTA tile 128x256, BK=16, 8 warps (2m x 4n) of 64x64, double-buffered
// cp.async. Dynamic smem (61 KB).
// ======================================================================
#define SA 20
#define GBM 128
#define GBN 256
#define A_TILE (GBM * SA)           /* floats per stage */
#define B_TILE (GBN * SA)
#define GEMM_SMEM ((2 * A_TILE + 2 * B_TILE) * 4)

__global__ __launch_bounds__(256, 1) void gemm_mma(
    const float* __restrict__ A, const float* __restrict__ W,
    const float* __restrict__ bias, float* __restrict__ C,
    int ldc, int K, float alpha)
{
    extern __shared__ __align__(16) float smf[];
    float* As_ = smf;                 // [2][128][SA]
    float* Bs_ = smf + 2 * A_TILE;    // [2][256][SA]

    const int tid  = threadIdx.x;
    const int lane = tid & 31, w = tid >> 5;
    const int g = lane >> 2, t = lane & 3;
    const int wm = (w & 1) * 64, wn = (w >> 1) * 64;
    const int bm = blockIdx.y * GBM, bn = blockIdx.x * GBN;

    const int r  = tid >> 2;          // loader row 0..63
    const int c4 = (tid & 3) << 2;    // loader col 0,4,8,12

    const float* aBase = A + (size_t)(bm + r) * K + c4;
    const float* bBase = W + (size_t)(bn + r) * K + c4;
    const size_t rowskip = (size_t)64 * K;

    float acc[4][8][4];
#pragma unroll
    for (int mi = 0; mi < 4; ++mi)
#pragma unroll
        for (int ni = 0; ni < 8; ++ni)
#pragma unroll
            for (int e = 0; e < 4; ++e) acc[mi][ni][e] = 0.f;

    const int kiters = K >> 4;

    // prologue: stage 0
    {
        cp_async16(smem_u32(&As_[r * SA + c4]), aBase);
        cp_async16(smem_u32(&As_[(r + 64) * SA + c4]), aBase + rowskip);
        cp_async16(smem_u32(&Bs_[r * SA + c4]), bBase);
        cp_async16(smem_u32(&Bs_[(r + 64) * SA + c4]), bBase + rowskip);
        cp_async16(smem_u32(&Bs_[(r + 128) * SA + c4]), bBase + 2 * rowskip);
        cp_async16(smem_u32(&Bs_[(r + 192) * SA + c4]), bBase + 3 * rowskip);
        asm volatile("cp.async.commit_group;" ::: "memory");
    }

    for (int it = 0; it < kiters; ++it) {
        const int buf = it & 1;
        if (it + 1 < kiters) {
            const float* ag = aBase + (size_t)(it + 1) * 16;
            const float* bg = bBase + (size_t)(it + 1) * 16;
            float* An = As_ + (buf ^ 1) * A_TILE;
            float* Bn = Bs_ + (buf ^ 1) * B_TILE;
            cp_async16(smem_u32(&An[r * SA + c4]), ag);
            cp_async16(smem_u32(&An[(r + 64) * SA + c4]), ag + rowskip);
            cp_async16(smem_u32(&Bn[r * SA + c4]), bg);
            cp_async16(smem_u32(&Bn[(r + 64) * SA + c4]), bg + rowskip);
            cp_async16(smem_u32(&Bn[(r + 128) * SA + c4]), bg + 2 * rowskip);
            cp_async16(smem_u32(&Bn[(r + 192) * SA + c4]), bg + 3 * rowskip);
            asm volatile("cp.async.commit_group;" ::: "memory");
            asm volatile("cp.async.wait_group 1;" ::: "memory");
        } else {
            asm volatile("cp.async.wait_group 0;" ::: "memory");
        }
        __syncthreads();

        const float* Ab = As_ + buf * A_TILE;
        const float* Bb = Bs_ + buf * B_TILE;

#pragma unroll
        for (int ks = 0; ks < 16; ks += 8) {
            uint32_t af[4][4], bf[8][2];
#pragma unroll
            for (int mi = 0; mi < 4; ++mi) {
                const int mr = wm + 16 * mi + g;
                af[mi][0] = f2tf32(Ab[mr * SA + ks + t]);
                af[mi][1] = f2tf32(Ab[(mr + 8) * SA + ks + t]);
                af[mi][2] = f2tf32(Ab[mr * SA + ks + t + 4]);
                af[mi][3] = f2tf32(Ab[(mr + 8) * SA + ks + t + 4]);
            }
#pragma unroll
            for (int ni = 0; ni < 8; ++ni) {
                const int nr = wn + 8 * ni + g;
                bf[ni][0] = f2tf32(Bb[nr * SA + ks + t]);
                bf[ni][1] = f2tf32(Bb[nr * SA + ks + t + 4]);
            }
#pragma unroll
            for (int mi = 0; mi < 4; ++mi)
#pragma unroll
                for (int ni = 0; ni < 8; ++ni)
                    mma_tf32_16n8k8(acc[mi][ni], af[mi], bf[ni]);
        }
        __syncthreads();
    }

    // epilogue
#pragma unroll
    for (int mi = 0; mi < 4; ++mi) {
        const int row0 = bm + wm + 16 * mi + g;
#pragma unroll
        for (int ni = 0; ni < 8; ++ni) {
            const int col = bn + wn + 8 * ni + 2 * t;
            const float b0 = bias[col], b1 = bias[col + 1];
            float2 v0, v1;
            v0.x = alpha * (acc[mi][ni][0] + b0);
            v0.y = alpha * (acc[mi][ni][1] + b1);
            v1.x = alpha * (acc[mi][ni][2] + b0);
            v1.y = alpha * (acc[mi][ni][3] + b1);
            *(float2*)&C[(size_t)row0 * ldc + col]       = v0;
            *(float2*)&C[(size_t)(row0 + 8) * ldc + col] = v1;
        }
    }
}

// ======================================================================
// Tensor-core flash attention (tf32 mma.sync) — unchanged from round 7
// ======================================================================
#define SQ 132
#define SP 68
#define ATTN2_FLOATS (128*SQ + 64*SQ + 64*SQ + 128*SP + 64)
#define ATTN2_SMEM (ATTN2_FLOATS * 4)

__global__ __launch_bounds__(256, 1) void attn_mma(
    const float* __restrict__ pastk, const float* __restrict__ pastv,
    const int* __restrict__ mask)
{
    extern __shared__ __align__(16) float sm[];
    float* Qs = sm;                 // [128][SQ]
    float* Ks = Qs + 128 * SQ;      // [64][SQ]
    float* Vs = Ks + 64 * SQ;       // [64][SQ]
    float* Ps = Vs + 64 * SQ;       // [128][SP]
    float* Ms = Ps + 128 * SP;      // [64]

    const int tid = threadIdx.x;
    const int lane = tid & 31, w = tid >> 5;
    const int g = lane >> 2, t = lane & 3;
    const int c2 = 2 * t;
    const int qt = blockIdx.x, h = blockIdx.y, b = blockIdx.z;
    const int hkv = h >> 2;
    const int q0 = qt * 128;

    for (int e = tid; e < 128 * 32; e += 256) {
        int r = e >> 5, c4 = (e & 31) << 2;
        float4 v = *(const float4*)(g_q + (size_t)(b * QL + q0 + r) * HIDN + h * HD + c4);
        float4 o = {f2tf32f(v.x), f2tf32f(v.y), f2tf32f(v.z), f2tf32f(v.w)};
        *(float4*)&Qs[r * SQ + c4] = o;
    }

    float m0 = -1e30f, m1 = -1e30f, l0 = 0.f, l1 = 0.f;
    float o_[16][4];
#pragma unroll
    for (int nt = 0; nt < 16; ++nt)
#pragma unroll
        for (int e = 0; e < 4; ++e) o_[nt][e] = 0.f;

    const uint32_t* Qu = (const uint32_t*)Qs;
    const uint32_t* Ku = (const uint32_t*)Ks;
    const uint32_t* Vu = (const uint32_t*)Vs;
    const uint32_t* Pu = (const uint32_t*)Ps;

    const int rA0 = (16 * w + g) * SQ;
    const int rA1 = (16 * w + g + 8) * SQ;
    const int pA0 = (16 * w + g) * SP;
    const int pA1 = (16 * w + g + 8) * SP;

    for (int kt = 0; kt < SKV / 64; ++kt) {
        const int kv0 = kt * 64;
        __syncthreads();

        for (int e = tid; e < 64 * 32; e += 256) {
            int r = e >> 5, c4 = (e & 31) << 2;
            int jg = kv0 + r;
            const float *ksrc, *vsrc;
            if (jg < PAST) {
                size_t base = ((size_t)(b * NKV + hkv) * PAST + jg) * HD + c4;
                ksrc = pastk + base; vsrc = pastv + base;
            } else {
                size_t base = (size_t)(b * QL + (jg - PAST)) * (NKV * HD) + hkv * HD + c4;
                ksrc = g_k + base; vsrc = g_v + base;
            }
            float4 kk = *(const float4*)ksrc;
            float4 vv = *(const float4*)vsrc;
            float4 ko = {f2tf32f(kk.x), f2tf32f(kk.y), f2tf32f(kk.z), f2tf32f(kk.w)};
            float4 vo = {f2tf32f(vv.x), f2tf32f(vv.y), f2tf32f(vv.z), f2tf32f(vv.w)};
            *(float4*)&Ks[r * SQ + c4] = ko;
            *(float4*)&Vs[r * SQ + c4] = vo;
        }
        if (tid < 64)
            Ms[tid] = (mask[b * SKV + kv0 + tid] == 0) ? 0.0f : -1e9f;
        __syncthreads();

        float s[8][4];
#pragma unroll
        for (int nt = 0; nt < 8; ++nt)
#pragma unroll
            for (int e = 0; e < 4; ++e) s[nt][e] = 0.f;

#pragma unroll
        for (int ks = 0; ks < 128; ks += 8) {
            uint32_t a[4] = {Qu[rA0 + ks + t], Qu[rA1 + ks + t],
                             Qu[rA0 + ks + t + 4], Qu[rA1 + ks + t + 4]};
#pragma unroll
            for (int nt = 0; nt < 8; ++nt) {
                uint32_t bb[2] = {Ku[(nt * 8 + g) * SQ + ks + t],
                                  Ku[(nt * 8 + g) * SQ + ks + t + 4]};
                mma_tf32_16n8k8(s[nt], a, bb);
            }
        }

        float rm0 = -1e30f, rm1 = -1e30f;
#pragma unroll
        for (int nt = 0; nt < 8; ++nt) {
            float mk0 = Ms[nt * 8 + c2], mk1 = Ms[nt * 8 + c2 + 1];
            s[nt][0] += mk0; s[nt][1] += mk1;
            s[nt][2] += mk0; s[nt][3] += mk1;
            rm0 = fmaxf(rm0, fmaxf(s[nt][0], s[nt][1]));
            rm1 = fmaxf(rm1, fmaxf(s[nt][2], s[nt][3]));
        }
        rm0 = fmaxf(rm0, __shfl_xor_sync(0xffffffffu, rm0, 1));
        rm0 = fmaxf(rm0, __shfl_xor_sync(0xffffffffu, rm0, 2));
        rm1 = fmaxf(rm1, __shfl_xor_sync(0xffffffffu, rm1, 1));
        rm1 = fmaxf(rm1, __shfl_xor_sync(0xffffffffu, rm1, 2));

        float mn0 = fmaxf(m0, rm0), mn1 = fmaxf(m1, rm1);
        float corr0 = __expf(m0 - mn0), corr1 = __expf(m1 - mn1);
        float rs0 = 0.f, rs1 = 0.f;
#pragma unroll
        for (int nt = 0; nt < 8; ++nt) {
            float p0 = __expf(s[nt][0] - mn0);
            float p1 = __expf(s[nt][1] - mn0);
            float p2 = __expf(s[nt][2] - mn1);
            float p3 = __expf(s[nt][3] - mn1);
            rs0 += p0 + p1; rs1 += p2 + p3;
            Ps[pA0 + nt * 8 + c2]     = f2tf32f(p0);
            Ps[pA0 + nt * 8 + c2 + 1] = f2tf32f(p1);
            Ps[pA1 + nt * 8 + c2]     = f2tf32f(p2);
            Ps[pA1 + nt * 8 + c2 + 1] = f2tf32f(p3);
        }
        rs0 += __shfl_xor_sync(0xffffffffu, rs0, 1);
        rs0 += __shfl_xor_sync(0xffffffffu, rs0, 2);
        rs1 += __shfl_xor_sync(0xffffffffu, rs1, 1);
        rs1 += __shfl_xor_sync(0xffffffffu, rs1, 2);

        l0 = l0 * corr0 + rs0; m0 = mn0;
        l1 = l1 * corr1 + rs1; m1 = mn1;
#pragma unroll
        for (int nt = 0; nt < 16; ++nt) {
            o_[nt][0] *= corr0; o_[nt][1] *= corr0;
            o_[nt][2] *= corr1; o_[nt][3] *= corr1;
        }
        __syncwarp();

#pragma unroll
        for (int ks = 0; ks < 64; ks += 8) {
            uint32_t a[4] = {Pu[pA0 + ks + t], Pu[pA1 + ks + t],
                             Pu[pA0 + ks + t + 4], Pu[pA1 + ks + t + 4]};
#pragma unroll
            for (int nt = 0; nt < 16; ++nt) {
                uint32_t bb[2] = {Vu[(ks + t) * SQ + nt * 8 + g],
                                  Vu[(ks + t + 4) * SQ + nt * 8 + g]};
                mma_tf32_16n8k8(o_[nt], a, bb);
            }
        }
    }

    float i0 = 1.0f / l0, i1 = 1.0f / l1;
    size_t row0 = (size_t)(b * QL + q0 + 16 * w + g);
    size_t row1 = row0 + 8;
#pragma unroll
    for (int nt = 0; nt < 16; ++nt) {
        int col = h * HD + nt * 8 + c2;
        float2 v0 = {o_[nt][0] * i0, o_[nt][1] * i0};
        float2 v1 = {o_[nt][2] * i1, o_[nt][3] * i1};
        *(float2*)&g_att[row0 * HIDN + col] = v0;
        *(float2*)&g_att[row1 * HIDN + col] = v1;
    }
}

// ======================================================================
extern "C" void kernel_launch(void* const* d_in, const int* in_sizes, int n_in,
                              void* d_out, int out_size)
{
    (void)in_sizes; (void)n_in; (void)out_size;
    const float* hidden = (const float*)d_in[0];
    const float* pastk  = (const float*)d_in[1];
    const float* pastv  = (const float*)d_in[2];
    const int*   mask   = (const int*)  d_in[3];
    const float* Wq = (const float*)d_in[4];
    const float* bq = (const float*)d_in[5];
    const float* Wk = (const float*)d_in[6];
    const float* bk = (const float*)d_in[7];
    const float* Wv = (const float*)d_in[8];
    const float* bv = (const float*)d_in[9];
    const float* Wo = (const float*)d_in[10];
    const float* bo = (const float*)d_in[11];
    float* out = (float*)d_out;

    float *qp, *kp, *vp, *ap;
    cudaGetSymbolAddress((void**)&qp, g_q);
    cudaGetSymbolAddress((void**)&kp, g_k);
    cudaGetSymbolAddress((void**)&vp, g_v);
    cudaGetSymbolAddress((void**)&ap, g_att);

    cudaFuncSetAttribute(gemm_mma, cudaFuncAttributeMaxDynamicSharedMemorySize, GEMM_SMEM);
    cudaFuncSetAttribute(attn_mma, cudaFuncAttributeMaxDynamicSharedMemorySize, ATTN2_SMEM);

    const float alpha_q = 0.08838834764831845f;  // SCALING / sqrt(HEAD_DIM)
    dim3 blk(256);

    // QKV projections (tf32 tensor cores)
    gemm_mma<<<dim3(HIDN / GBN, MROWS / GBM), blk, GEMM_SMEM>>>(hidden, Wq, bq, qp, HIDN, HIDN, alpha_q);
    gemm_mma<<<dim3((NKV * HD) / GBN, MROWS / GBM), blk, GEMM_SMEM>>>(hidden, Wk, bk, kp, NKV * HD, HIDN, 1.0f);
    gemm_mma<<<dim3((NKV * HD) / GBN, MROWS / GBM), blk, GEMM_SMEM>>>(hidden, Wv, bv, vp, NKV * HD, HIDN, 1.0f);

    // attention (tf32 tensor cores)
    attn_mma<<<dim3(QL / 128, NH, BB), blk, ATTN2_SMEM>>>(pastk, pastv, mask);

    // output projection
    gemm_mma<<<dim3(HIDN / GBN, MROWS / GBM), blk, GEMM_SMEM>>>(ap, Wo, bo, out, HIDN, HIDN, 1.0f);
}

// round 11
// speedup vs baseline: 4.8763x; 1.1645x over previous
#include <cuda_runtime.h>
#include <cstdint>
#include <math.h>

#define HIDN 4096
#define NH   32
#define NKV  8
#define HD   128
#define BB   4
#define QL   1024
#define PAST 1024
#define SKV  2048
#define MROWS (BB*QL)   /* 4096 */

// -------- scratch (device globals; no allocation allowed) --------
__device__ float g_q[(size_t)MROWS * HIDN];        // [B*Sq, H*D]
__device__ float g_k[(size_t)MROWS * (NKV * HD)];  // [B*Sq, Hkv*D]
__device__ float g_v[(size_t)MROWS * (NKV * HD)];
__device__ float g_att[(size_t)MROWS * HIDN];      // [B*Sq, H*D]

// ======================================================================
// helpers
// ======================================================================
__device__ __forceinline__ uint32_t smem_u32(const void* p) {
    uint32_t a;
    asm("{ .reg .u64 t; cvta.to.shared.u64 t, %1; cvt.u32.u64 %0, t; }" : "=r"(a) : "l"(p));
    return a;
}

__device__ __forceinline__ void cp_async16(uint32_t s, const void* g) {
    asm volatile("cp.async.cg.shared.global [%0], [%1], 16;" :: "r"(s), "l"(g) : "memory");
}

__device__ __forceinline__ uint32_t f2tf32(float x) {
    uint32_t r;
    asm("cvt.rna.tf32.f32 %0, %1;" : "=r"(r) : "f"(x));
    return r;
}
__device__ __forceinline__ float f2tf32f(float x) { return __uint_as_float(f2tf32(x)); }

__device__ __forceinline__ void mma_tf32_16n8k8(float* c, const uint32_t* a, const uint32_t* b) {
    asm volatile(
        "mma.sync.aligned.m16n8k8.row.col.f32.tf32.tf32.f32 "
        "{%0,%1,%2,%3}, {%4,%5,%6,%7}, {%8,%9}, {%0,%1,%2,%3};"
        : "+f"(c[0]), "+f"(c[1]), "+f"(c[2]), "+f"(c[3])
        : "r"(a[0]), "r"(a[1]), "r"(a[2]), "r"(a[3]), "r"(b[0]), "r"(b[1]));
}

// ======================================================================
// tf32 mma.sync GEMM-NT: C[m,n] = alpha*( sum_k A[m,k]*W[n,k] + bias[n] )
// CTA tile 128x128, BK=16, 8 warps (2m x 4n) of 64x32, double-buffered
// cp.async. 40 KB static smem -> 2 CTAs/SM (reg-capped by launch bounds).
// ======================================================================
#define SA 20

__global__ __launch_bounds__(256, 2) void gemm_mma(
    const float* __restrict__ A, const float* __restrict__ W,
    const float* __restrict__ bias, float* __restrict__ C,
    int ldc, int K, float alpha)
{
    __shared__ float As[2][128][SA];
    __shared__ float Bs[2][128][SA];

    const int tid  = threadIdx.x;
    const int lane = tid & 31, w = tid >> 5;
    const int g = lane >> 2, t = lane & 3;
    const int wm = (w & 1) * 64, wn = (w >> 1) * 32;
    const int bm = blockIdx.y * 128, bn = blockIdx.x * 128;

    const int r  = tid >> 2;
    const int c4 = (tid & 3) << 2;

    const float* aBase = A + (size_t)(bm + r) * K + c4;
    const float* bBase = W + (size_t)(bn + r) * K + c4;
    const size_t rowskip = (size_t)64 * K;

    float acc[4][4][4];
#pragma unroll
    for (int mi = 0; mi < 4; ++mi)
#pragma unroll
        for (int ni = 0; ni < 4; ++ni)
#pragma unroll
            for (int e = 0; e < 4; ++e) acc[mi][ni][e] = 0.f;

    const int kiters = K >> 4;

    {
        cp_async16(smem_u32(&As[0][r][c4]), aBase);
        cp_async16(smem_u32(&As[0][r + 64][c4]), aBase + rowskip);
        cp_async16(smem_u32(&Bs[0][r][c4]), bBase);
        cp_async16(smem_u32(&Bs[0][r + 64][c4]), bBase + rowskip);
        asm volatile("cp.async.commit_group;" ::: "memory");
    }

    for (int it = 0; it < kiters; ++it) {
        const int buf = it & 1;
        if (it + 1 < kiters) {
            const float* ag = aBase + (size_t)(it + 1) * 16;
            const float* bg = bBase + (size_t)(it + 1) * 16;
            cp_async16(smem_u32(&As[buf ^ 1][r][c4]), ag);
            cp_async16(smem_u32(&As[buf ^ 1][r + 64][c4]), ag + rowskip);
            cp_async16(smem_u32(&Bs[buf ^ 1][r][c4]), bg);
            cp_async16(smem_u32(&Bs[buf ^ 1][r + 64][c4]), bg + rowskip);
            asm volatile("cp.async.commit_group;" ::: "memory");
            asm volatile("cp.async.wait_group 1;" ::: "memory");
        } else {
            asm volatile("cp.async.wait_group 0;" ::: "memory");
        }
        __syncthreads();

#pragma unroll
        for (int ks = 0; ks < 16; ks += 8) {
            uint32_t af[4][4], bf[4][2];
#pragma unroll
            for (int mi = 0; mi < 4; ++mi) {
                const int mr = wm + 16 * mi + g;
                af[mi][0] = f2tf32(As[buf][mr][ks + t]);
                af[mi][1] = f2tf32(As[buf][mr + 8][ks + t]);
                af[mi][2] = f2tf32(As[buf][mr][ks + t + 4]);
                af[mi][3] = f2tf32(As[buf][mr + 8][ks + t + 4]);
            }
#pragma unroll
            for (int ni = 0; ni < 4; ++ni) {
                const int nr = wn + 8 * ni + g;
                bf[ni][0] = f2tf32(Bs[buf][nr][ks + t]);
                bf[ni][1] = f2tf32(Bs[buf][nr][ks + t + 4]);
            }
#pragma unroll
            for (int mi = 0; mi < 4; ++mi)
#pragma unroll
                for (int ni = 0; ni < 4; ++ni)
                    mma_tf32_16n8k8(acc[mi][ni], af[mi], bf[ni]);
        }
        __syncthreads();
    }

#pragma unroll
    for (int mi = 0; mi < 4; ++mi) {
        const int row0 = bm + wm + 16 * mi + g;
#pragma unroll
        for (int ni = 0; ni < 4; ++ni) {
            const int col = bn + wn + 8 * ni + 2 * t;
            const float b0 = bias[col], b1 = bias[col + 1];
            float2 v0, v1;
            v0.x = alpha * (acc[mi][ni][0] + b0);
            v0.y = alpha * (acc[mi][ni][1] + b1);
            v1.x = alpha * (acc[mi][ni][2] + b0);
            v1.y = alpha * (acc[mi][ni][3] + b1);
            *(float2*)&C[(size_t)row0 * ldc + col]       = v0;
            *(float2*)&C[(size_t)(row0 + 8) * ldc + col] = v1;
        }
    }
}

// ======================================================================
// Tensor-core flash attention (tf32 mma.sync)
// V gets its own smem stride (136, ≡8 mod 32) -> conflict-free PV B reads.
// ======================================================================
#define SQ 132
#define SV 136
#define SP 68
#define ATTN2_FLOATS (128*SQ + 64*SQ + 64*SV + 128*SP + 64)
#define ATTN2_SMEM (ATTN2_FLOATS * 4)

__global__ __launch_bounds__(256, 1) void attn_mma(
    const float* __restrict__ pastk, const float* __restrict__ pastv,
    const int* __restrict__ mask)
{
    extern __shared__ __align__(16) float sm[];
    float* Qs = sm;                 // [128][SQ]
    float* Ks = Qs + 128 * SQ;      // [64][SQ]
    float* Vs = Ks + 64 * SQ;       // [64][SV]
    float* Ps = Vs + 64 * SV;       // [128][SP]
    float* Ms = Ps + 128 * SP;      // [64]

    const int tid = threadIdx.x;
    const int lane = tid & 31, w = tid >> 5;
    const int g = lane >> 2, t = lane & 3;
    const int c2 = 2 * t;
    const int qt = blockIdx.x, h = blockIdx.y, b = blockIdx.z;
    const int hkv = h >> 2;
    const int q0 = qt * 128;

    for (int e = tid; e < 128 * 32; e += 256) {
        int r = e >> 5, c4 = (e & 31) << 2;
        float4 v = *(const float4*)(g_q + (size_t)(b * QL + q0 + r) * HIDN + h * HD + c4);
        float4 o = {f2tf32f(v.x), f2tf32f(v.y), f2tf32f(v.z), f2tf32f(v.w)};
        *(float4*)&Qs[r * SQ + c4] = o;
    }

    float m0 = -1e30f, m1 = -1e30f, l0 = 0.f, l1 = 0.f;
    float o_[16][4];
#pragma unroll
    for (int nt = 0; nt < 16; ++nt)
#pragma unroll
        for (int e = 0; e < 4; ++e) o_[nt][e] = 0.f;

    const uint32_t* Qu = (const uint32_t*)Qs;
    const uint32_t* Ku = (const uint32_t*)Ks;
    const uint32_t* Vu = (const uint32_t*)Vs;
    const uint32_t* Pu = (const uint32_t*)Ps;

    const int rA0 = (16 * w + g) * SQ;
    const int rA1 = (16 * w + g + 8) * SQ;
    const int pA0 = (16 * w + g) * SP;
    const int pA1 = (16 * w + g + 8) * SP;

    for (int kt = 0; kt < SKV / 64; ++kt) {
        const int kv0 = kt * 64;
        __syncthreads();

        for (int e = tid; e < 64 * 32; e += 256) {
            int r = e >> 5, c4 = (e & 31) << 2;
            int jg = kv0 + r;
            const float *ksrc, *vsrc;
            if (jg < PAST) {
                size_t base = ((size_t)(b * NKV + hkv) * PAST + jg) * HD + c4;
                ksrc = pastk + base; vsrc = pastv + base;
            } else {
                size_t base = (size_t)(b * QL + (jg - PAST)) * (NKV * HD) + hkv * HD + c4;
                ksrc = g_k + base; vsrc = g_v + base;
            }
            float4 kk = *(const float4*)ksrc;
            float4 vv = *(const float4*)vsrc;
            float4 ko = {f2tf32f(kk.x), f2tf32f(kk.y), f2tf32f(kk.z), f2tf32f(kk.w)};
            float4 vo = {f2tf32f(vv.x), f2tf32f(vv.y), f2tf32f(vv.z), f2tf32f(vv.w)};
            *(float4*)&Ks[r * SQ + c4] = ko;
            *(float4*)&Vs[r * SV + c4] = vo;
        }
        if (tid < 64)
            Ms[tid] = (mask[b * SKV + kv0 + tid] == 0) ? 0.0f : -1e9f;
        __syncthreads();

        float s[8][4];
#pragma unroll
        for (int nt = 0; nt < 8; ++nt)
#pragma unroll
            for (int e = 0; e < 4; ++e) s[nt][e] = 0.f;

#pragma unroll
        for (int ks = 0; ks < 128; ks += 8) {
            uint32_t a[4] = {Qu[rA0 + ks + t], Qu[rA1 + ks + t],
                             Qu[rA0 + ks + t + 4], Qu[rA1 + ks + t + 4]};
#pragma unroll
            for (int nt = 0; nt < 8; ++nt) {
                uint32_t bb[2] = {Ku[(nt * 8 + g) * SQ + ks + t],
                                  Ku[(nt * 8 + g) * SQ + ks + t + 4]};
                mma_tf32_16n8k8(s[nt], a, bb);
            }
        }

        float rm0 = -1e30f, rm1 = -1e30f;
#pragma unroll
        for (int nt = 0; nt < 8; ++nt) {
            float mk0 = Ms[nt * 8 + c2], mk1 = Ms[nt * 8 + c2 + 1];
            s[nt][0] += mk0; s[nt][1] += mk1;
            s[nt][2] += mk0; s[nt][3] += mk1;
            rm0 = fmaxf(rm0, fmaxf(s[nt][0], s[nt][1]));
            rm1 = fmaxf(rm1, fmaxf(s[nt][2], s[nt][3]));
        }
        rm0 = fmaxf(rm0, __shfl_xor_sync(0xffffffffu, rm0, 1));
        rm0 = fmaxf(rm0, __shfl_xor_sync(0xffffffffu, rm0, 2));
        rm1 = fmaxf(rm1, __shfl_xor_sync(0xffffffffu, rm1, 1));
        rm1 = fmaxf(rm1, __shfl_xor_sync(0xffffffffu, rm1, 2));

        float mn0 = fmaxf(m0, rm0), mn1 = fmaxf(m1, rm1);
        float corr0 = __expf(m0 - mn0), corr1 = __expf(m1 - mn1);
        float rs0 = 0.f, rs1 = 0.f;
#pragma unroll
        for (int nt = 0; nt < 8; ++nt) {
            float p0 = __expf(s[nt][0] - mn0);
            float p1 = __expf(s[nt][1] - mn0);
            float p2 = __expf(s[nt][2] - mn1);
            float p3 = __expf(s[nt][3] - mn1);
            rs0 += p0 + p1; rs1 += p2 + p3;
            Ps[pA0 + nt * 8 + c2]     = f2tf32f(p0);
            Ps[pA0 + nt * 8 + c2 + 1] = f2tf32f(p1);
            Ps[pA1 + nt * 8 + c2]     = f2tf32f(p2);
            Ps[pA1 + nt * 8 + c2 + 1] = f2tf32f(p3);
        }
        rs0 += __shfl_xor_sync(0xffffffffu, rs0, 1);
        rs0 += __shfl_xor_sync(0xffffffffu, rs0, 2);
        rs1 += __shfl_xor_sync(0xffffffffu, rs1, 1);
        rs1 += __shfl_xor_sync(0xffffffffu, rs1, 2);

        l0 = l0 * corr0 + rs0; m0 = mn0;
        l1 = l1 * corr1 + rs1; m1 = mn1;
#pragma unroll
        for (int nt = 0; nt < 16; ++nt) {
            o_[nt][0] *= corr0; o_[nt][1] *= corr0;
            o_[nt][2] *= corr1; o_[nt][3] *= corr1;
        }
        __syncwarp();

#pragma unroll
        for (int ks = 0; ks < 64; ks += 8) {
            uint32_t a[4] = {Pu[pA0 + ks + t], Pu[pA1 + ks + t],
                             Pu[pA0 + ks + t + 4], Pu[pA1 + ks + t + 4]};
#pragma unroll
            for (int nt = 0; nt < 16; ++nt) {
                uint32_t bb[2] = {Vu[(ks + t) * SV + nt * 8 + g],
                                  Vu[(ks + t + 4) * SV + nt * 8 + g]};
                mma_tf32_16n8k8(o_[nt], a, bb);
            }
        }
    }

    float i0 = 1.0f / l0, i1 = 1.0f / l1;
    size_t row0 = (size_t)(b * QL + q0 + 16 * w + g);
    size_t row1 = row0 + 8;
#pragma unroll
    for (int nt = 0; nt < 16; ++nt) {
        int col = h * HD + nt * 8 + c2;
        float2 v0 = {o_[nt][0] * i0, o_[nt][1] * i0};
        float2 v1 = {o_[nt][2] * i1, o_[nt][3] * i1};
        *(float2*)&g_att[row0 * HIDN + col] = v0;
        *(float2*)&g_att[row1 * HIDN + col] = v1;
    }
}

// ======================================================================
extern "C" void kernel_launch(void* const* d_in, const int* in_sizes, int n_in,
                              void* d_out, int out_size)
{
    (void)in_sizes; (void)n_in; (void)out_size;
    const float* hidden = (const float*)d_in[0];
    const float* pastk  = (const float*)d_in[1];
    const float* pastv  = (const float*)d_in[2];
    const int*   mask   = (const int*)  d_in[3];
    const float* Wq = (const float*)d_in[4];
    const float* bq = (const float*)d_in[5];
    const float* Wk = (const float*)d_in[6];
    const float* bk = (const float*)d_in[7];
    const float* Wv = (const float*)d_in[8];
    const float* bv = (const float*)d_in[9];
    const float* Wo = (const float*)d_in[10];
    const float* bo = (const float*)d_in[11];
    float* out = (float*)d_out;

    float *qp, *kp, *vp, *ap;
    cudaGetSymbolAddress((void**)&qp, g_q);
    cudaGetSymbolAddress((void**)&kp, g_k);
    cudaGetSymbolAddress((void**)&vp, g_v);
    cudaGetSymbolAddress((void**)&ap, g_att);

    cudaFuncSetAttribute(attn_mma, cudaFuncAttributeMaxDynamicSharedMemorySize, ATTN2_SMEM);

    const float alpha_q = 0.08838834764831845f;  // SCALING / sqrt(HEAD_DIM)
    dim3 blk(256);

    // QKV projections (tf32 tensor cores)
    gemm_mma<<<dim3(HIDN / 128, MROWS / 128), blk>>>(hidden, Wq, bq, qp, HIDN, HIDN, alpha_q);
    gemm_mma<<<dim3((NKV * HD) / 128, MROWS / 128), blk>>>(hidden, Wk, bk, kp, NKV * HD, HIDN, 1.0f);
    gemm_mma<<<dim3((NKV * HD) / 128, MROWS / 128), blk>>>(hidden, Wv, bv, vp, NKV * HD, HIDN, 1.0f);

    // attention (tf32 tensor cores)
    attn_mma<<<dim3(QL / 128, NH, BB), blk, ATTN2_SMEM>>>(pastk, pastv, mask);

    // output projection
    gemm_mma<<<dim3(HIDN / 128, MROWS / 128), blk>>>(ap, Wo, bo, out, HIDN, HIDN, 1.0f);
}

// round 12
// speedup vs baseline: 4.9675x; 1.0187x over previous
#include <cuda_runtime.h>
#include <cstdint>
#include <math.h>

#define HIDN 4096
#define NH   32
#define NKV  8
#define HD   128
#define BB   4
#define QL   1024
#define PAST 1024
#define SKV  2048
#define MROWS (BB*QL)   /* 4096 */

// -------- scratch (device globals; no allocation allowed) --------
__device__ float g_q[(size_t)MROWS * HIDN];        // [B*Sq, H*D]
__device__ float g_k[(size_t)MROWS * (NKV * HD)];  // [B*Sq, Hkv*D]
__device__ float g_v[(size_t)MROWS * (NKV * HD)];
__device__ float g_att[(size_t)MROWS * HIDN];      // [B*Sq, H*D]

// ======================================================================
// helpers
// ======================================================================
__device__ __forceinline__ uint32_t smem_u32(const void* p) {
    uint32_t a;
    asm("{ .reg .u64 t; cvta.to.shared.u64 t, %1; cvt.u32.u64 %0, t; }" : "=r"(a) : "l"(p));
    return a;
}

__device__ __forceinline__ void cp_async16(uint32_t s, const void* g) {
    asm volatile("cp.async.cg.shared.global [%0], [%1], 16;" :: "r"(s), "l"(g) : "memory");
}

__device__ __forceinline__ uint32_t f2tf32(float x) {
    uint32_t r;
    asm("cvt.rna.tf32.f32 %0, %1;" : "=r"(r) : "f"(x));
    return r;
}
__device__ __forceinline__ float f2tf32f(float x) { return __uint_as_float(f2tf32(x)); }

__device__ __forceinline__ void mma_tf32_16n8k8(float* c, const uint32_t* a, const uint32_t* b) {
    asm volatile(
        "mma.sync.aligned.m16n8k8.row.col.f32.tf32.tf32.f32 "
        "{%0,%1,%2,%3}, {%4,%5,%6,%7}, {%8,%9}, {%0,%1,%2,%3};"
        : "+f"(c[0]), "+f"(c[1]), "+f"(c[2]), "+f"(c[3])
        : "r"(a[0]), "r"(a[1]), "r"(a[2]), "r"(a[3]), "r"(b[0]), "r"(b[1]));
}

// ======================================================================
// tf32 mma.sync GEMM-NT (unchanged from round 11): 128x128 tile, 2 CTA/SM
// ======================================================================
#define SA 20

__global__ __launch_bounds__(256, 2) void gemm_mma(
    const float* __restrict__ A, const float* __restrict__ W,
    const float* __restrict__ bias, float* __restrict__ C,
    int ldc, int K, float alpha)
{
    __shared__ float As[2][128][SA];
    __shared__ float Bs[2][128][SA];

    const int tid  = threadIdx.x;
    const int lane = tid & 31, w = tid >> 5;
    const int g = lane >> 2, t = lane & 3;
    const int wm = (w & 1) * 64, wn = (w >> 1) * 32;
    const int bm = blockIdx.y * 128, bn = blockIdx.x * 128;

    const int r  = tid >> 2;
    const int c4 = (tid & 3) << 2;

    const float* aBase = A + (size_t)(bm + r) * K + c4;
    const float* bBase = W + (size_t)(bn + r) * K + c4;
    const size_t rowskip = (size_t)64 * K;

    float acc[4][4][4];
#pragma unroll
    for (int mi = 0; mi < 4; ++mi)
#pragma unroll
        for (int ni = 0; ni < 4; ++ni)
#pragma unroll
            for (int e = 0; e < 4; ++e) acc[mi][ni][e] = 0.f;

    const int kiters = K >> 4;

    {
        cp_async16(smem_u32(&As[0][r][c4]), aBase);
        cp_async16(smem_u32(&As[0][r + 64][c4]), aBase + rowskip);
        cp_async16(smem_u32(&Bs[0][r][c4]), bBase);
        cp_async16(smem_u32(&Bs[0][r + 64][c4]), bBase + rowskip);
        asm volatile("cp.async.commit_group;" ::: "memory");
    }

    for (int it = 0; it < kiters; ++it) {
        const int buf = it & 1;
        if (it + 1 < kiters) {
            const float* ag = aBase + (size_t)(it + 1) * 16;
            const float* bg = bBase + (size_t)(it + 1) * 16;
            cp_async16(smem_u32(&As[buf ^ 1][r][c4]), ag);
            cp_async16(smem_u32(&As[buf ^ 1][r + 64][c4]), ag + rowskip);
            cp_async16(smem_u32(&Bs[buf ^ 1][r][c4]), bg);
            cp_async16(smem_u32(&Bs[buf ^ 1][r + 64][c4]), bg + rowskip);
            asm volatile("cp.async.commit_group;" ::: "memory");
            asm volatile("cp.async.wait_group 1;" ::: "memory");
        } else {
            asm volatile("cp.async.wait_group 0;" ::: "memory");
        }
        __syncthreads();

#pragma unroll
        for (int ks = 0; ks < 16; ks += 8) {
            uint32_t af[4][4], bf[4][2];
#pragma unroll
            for (int mi = 0; mi < 4; ++mi) {
                const int mr = wm + 16 * mi + g;
                af[mi][0] = f2tf32(As[buf][mr][ks + t]);
                af[mi][1] = f2tf32(As[buf][mr + 8][ks + t]);
                af[mi][2] = f2tf32(As[buf][mr][ks + t + 4]);
                af[mi][3] = f2tf32(As[buf][mr + 8][ks + t + 4]);
            }
#pragma unroll
            for (int ni = 0; ni < 4; ++ni) {
                const int nr = wn + 8 * ni + g;
                bf[ni][0] = f2tf32(Bs[buf][nr][ks + t]);
                bf[ni][1] = f2tf32(Bs[buf][nr][ks + t + 4]);
            }
#pragma unroll
            for (int mi = 0; mi < 4; ++mi)
#pragma unroll
                for (int ni = 0; ni < 4; ++ni)
                    mma_tf32_16n8k8(acc[mi][ni], af[mi], bf[ni]);
        }
        __syncthreads();
    }

#pragma unroll
    for (int mi = 0; mi < 4; ++mi) {
        const int row0 = bm + wm + 16 * mi + g;
#pragma unroll
        for (int ni = 0; ni < 4; ++ni) {
            const int col = bn + wn + 8 * ni + 2 * t;
            const float b0 = bias[col], b1 = bias[col + 1];
            float2 v0, v1;
            v0.x = alpha * (acc[mi][ni][0] + b0);
            v0.y = alpha * (acc[mi][ni][1] + b1);
            v1.x = alpha * (acc[mi][ni][2] + b0);
            v1.y = alpha * (acc[mi][ni][3] + b1);
            *(float2*)&C[(size_t)row0 * ldc + col]       = v0;
            *(float2*)&C[(size_t)(row0 + 8) * ldc + col] = v1;
        }
    }
}

// ======================================================================
// Tensor-core flash attention with cp.async K/V pipeline.
// K double-buffered (prefetched 1 tile ahead), V single-buffered
// (load overlaps the S-phase). In-place RNA tf32 conversion passes keep
// numerics identical to round 11.
// ======================================================================
#define SQ 132
#define SV 136
#define SP 68
#define NKT (SKV / 64)
#define ATTN2_FLOATS (128*SQ + 2*64*SQ + 64*SV + 128*SP)
#define ATTN2_SMEM (ATTN2_FLOATS * 4)   /* 204800 B */

__global__ __launch_bounds__(256, 1) void attn_mma(
    const float* __restrict__ pastk, const float* __restrict__ pastv,
    const int* __restrict__ mask)
{
    extern __shared__ __align__(16) float sm[];
    float* Qs = sm;                    // [128][SQ]
    float* Kb = Qs + 128 * SQ;         // [2][64][SQ]
    float* Vs = Kb + 2 * 64 * SQ;      // [64][SV]
    float* Ps = Vs + 64 * SV;          // [128][SP]

    const int tid = threadIdx.x;
    const int lane = tid & 31, w = tid >> 5;
    const int g = lane >> 2, t = lane & 3;
    const int c2 = 2 * t;
    const int qt = blockIdx.x, h = blockIdx.y, b = blockIdx.z;
    const int hkv = h >> 2;
    const int q0 = qt * 128;

    // loader index for this thread (8 float4s per 64x128 tile)
    const int lr = tid >> 5;             // base row 0..7 (step 8)
    const int lc4 = (tid & 31) << 2;     // col 0,4,...,124

    // global KV source for row jg, col lc4
    const float* kvbaseK;
    const float* kvbaseV;
    {
        kvbaseK = pastk; kvbaseV = pastv;  // placeholders; computed per row below
    }

    // ---- prefetch K tile 0 (raw fp32) ----
    {
#pragma unroll
        for (int rr = 0; rr < 8; ++rr) {
            int jg = 0 * 64 + lr + rr * 8;
            const float* ksrc;
            if (jg < PAST)
                ksrc = pastk + ((size_t)(b * NKV + hkv) * PAST + jg) * HD + lc4;
            else
                ksrc = g_k + (size_t)(b * QL + (jg - PAST)) * (NKV * HD) + hkv * HD + lc4;
            cp_async16(smem_u32(&Kb[(lr + rr * 8) * SQ + lc4]), ksrc);
        }
        asm volatile("cp.async.commit_group;" ::: "memory");
    }

    // ---- load Q tile, convert to tf32 ----
    for (int e = tid; e < 128 * 32; e += 256) {
        int r = e >> 5, c4 = (e & 31) << 2;
        float4 v = *(const float4*)(g_q + (size_t)(b * QL + q0 + r) * HIDN + h * HD + c4);
        float4 o = {f2tf32f(v.x), f2tf32f(v.y), f2tf32f(v.z), f2tf32f(v.w)};
        *(float4*)&Qs[r * SQ + c4] = o;
    }

    float m0 = -1e30f, m1 = -1e30f, l0 = 0.f, l1 = 0.f;
    float o_[16][4];
#pragma unroll
    for (int nt = 0; nt < 16; ++nt)
#pragma unroll
        for (int e = 0; e < 4; ++e) o_[nt][e] = 0.f;

    const uint32_t* Qu = (const uint32_t*)Qs;
    const uint32_t* Vu = (const uint32_t*)Vs;
    const uint32_t* Pu = (const uint32_t*)Ps;

    const int rA0 = (16 * w + g) * SQ;
    const int rA1 = (16 * w + g + 8) * SQ;
    const int pA0 = (16 * w + g) * SP;
    const int pA1 = (16 * w + g + 8) * SP;

    for (int kt = 0; kt < NKT; ++kt) {
        const int kv0 = kt * 64;
        const int cur = kt & 1;
        float* Kcur = Kb + cur * 64 * SQ;
        const uint32_t* Ku = (const uint32_t*)Kcur;

        // ---- issue V_kt (Vs freed by end-of-prev-iter barrier) ----
#pragma unroll
        for (int rr = 0; rr < 8; ++rr) {
            int jg = kv0 + lr + rr * 8;
            const float* vsrc;
            if (jg < PAST)
                vsrc = pastv + ((size_t)(b * NKV + hkv) * PAST + jg) * HD + lc4;
            else
                vsrc = g_v + (size_t)(b * QL + (jg - PAST)) * (NKV * HD) + hkv * HD + lc4;
            cp_async16(smem_u32(&Vs[(lr + rr * 8) * SV + lc4]), vsrc);
        }
        asm volatile("cp.async.commit_group;" ::: "memory");

        // ---- issue K_{kt+1} into alternate buffer (empty group on last iter) ----
        if (kt + 1 < NKT) {
            float* Knxt = Kb + (cur ^ 1) * 64 * SQ;
#pragma unroll
            for (int rr = 0; rr < 8; ++rr) {
                int jg = kv0 + 64 + lr + rr * 8;
                const float* ksrc;
                if (jg < PAST)
                    ksrc = pastk + ((size_t)(b * NKV + hkv) * PAST + jg) * HD + lc4;
                else
                    ksrc = g_k + (size_t)(b * QL + (jg - PAST)) * (NKV * HD) + hkv * HD + lc4;
                cp_async16(smem_u32(&Knxt[(lr + rr * 8) * SQ + lc4]), ksrc);
            }
        }
        asm volatile("cp.async.commit_group;" ::: "memory");

        // ---- mask values into registers ----
        int2 mv[8];
#pragma unroll
        for (int nt = 0; nt < 8; ++nt)
            mv[nt] = *(const int2*)&mask[b * SKV + kv0 + nt * 8 + c2];

        // ---- wait K_kt (leave V_kt + K_{kt+1} pending), convert in place ----
        asm volatile("cp.async.wait_group 2;" ::: "memory");
        __syncthreads();
        for (int e = tid; e < 64 * 32; e += 256) {
            int r = e >> 5, c4 = (e & 31) << 2;
            float4* p = (float4*)&Kcur[r * SQ + c4];
            float4 v = *p;
            float4 o = {f2tf32f(v.x), f2tf32f(v.y), f2tf32f(v.z), f2tf32f(v.w)};
            *p = o;
        }
        __syncthreads();

        // ---- S = Q K^T (warp: 16 x 64); V_kt load in flight underneath ----
        float s[8][4];
#pragma unroll
        for (int nt = 0; nt < 8; ++nt)
#pragma unroll
            for (int e = 0; e < 4; ++e) s[nt][e] = 0.f;

#pragma unroll
        for (int ks = 0; ks < 128; ks += 8) {
            uint32_t a[4] = {Qu[rA0 + ks + t], Qu[rA1 + ks + t],
                             Qu[rA0 + ks + t + 4], Qu[rA1 + ks + t + 4]};
#pragma unroll
            for (int nt = 0; nt < 8; ++nt) {
                uint32_t bb[2] = {Ku[(nt * 8 + g) * SQ + ks + t],
                                  Ku[(nt * 8 + g) * SQ + ks + t + 4]};
                mma_tf32_16n8k8(s[nt], a, bb);
            }
        }

        // ---- mask + online softmax (mask from registers) ----
        float rm0 = -1e30f, rm1 = -1e30f;
#pragma unroll
        for (int nt = 0; nt < 8; ++nt) {
            float mk0 = (mv[nt].x == 0) ? 0.0f : -1e9f;
            float mk1 = (mv[nt].y == 0) ? 0.0f : -1e9f;
            s[nt][0] += mk0; s[nt][1] += mk1;
            s[nt][2] += mk0; s[nt][3] += mk1;
            rm0 = fmaxf(rm0, fmaxf(s[nt][0], s[nt][1]));
            rm1 = fmaxf(rm1, fmaxf(s[nt][2], s[nt][3]));
        }
        rm0 = fmaxf(rm0, __shfl_xor_sync(0xffffffffu, rm0, 1));
        rm0 = fmaxf(rm0, __shfl_xor_sync(0xffffffffu, rm0, 2));
        rm1 = fmaxf(rm1, __shfl_xor_sync(0xffffffffu, rm1, 1));
        rm1 = fmaxf(rm1, __shfl_xor_sync(0xffffffffu, rm1, 2));

        float mn0 = fmaxf(m0, rm0), mn1 = fmaxf(m1, rm1);
        float corr0 = __expf(m0 - mn0), corr1 = __expf(m1 - mn1);
        float rs0 = 0.f, rs1 = 0.f;
#pragma unroll
        for (int nt = 0; nt < 8; ++nt) {
            float p0 = __expf(s[nt][0] - mn0);
            float p1 = __expf(s[nt][1] - mn0);
            float p2 = __expf(s[nt][2] - mn1);
            float p3 = __expf(s[nt][3] - mn1);
            rs0 += p0 + p1; rs1 += p2 + p3;
            Ps[pA0 + nt * 8 + c2]     = f2tf32f(p0);
            Ps[pA0 + nt * 8 + c2 + 1] = f2tf32f(p1);
            Ps[pA1 + nt * 8 + c2]     = f2tf32f(p2);
            Ps[pA1 + nt * 8 + c2 + 1] = f2tf32f(p3);
        }
        rs0 += __shfl_xor_sync(0xffffffffu, rs0, 1);
        rs0 += __shfl_xor_sync(0xffffffffu, rs0, 2);
        rs1 += __shfl_xor_sync(0xffffffffu, rs1, 1);
        rs1 += __shfl_xor_sync(0xffffffffu, rs1, 2);

        l0 = l0 * corr0 + rs0; m0 = mn0;
        l1 = l1 * corr1 + rs1; m1 = mn1;
#pragma unroll
        for (int nt = 0; nt < 16; ++nt) {
            o_[nt][0] *= corr0; o_[nt][1] *= corr0;
            o_[nt][2] *= corr1; o_[nt][3] *= corr1;
        }
        __syncwarp();

        // ---- wait V_kt (leave K_{kt+1} pending), convert in place ----
        asm volatile("cp.async.wait_group 1;" ::: "memory");
        __syncthreads();
        for (int e = tid; e < 64 * 32; e += 256) {
            int r = e >> 5, c4 = (e & 31) << 2;
            float4* p = (float4*)&Vs[r * SV + c4];
            float4 v = *p;
            float4 o = {f2tf32f(v.x), f2tf32f(v.y), f2tf32f(v.z), f2tf32f(v.w)};
            *p = o;
        }
        __syncthreads();

        // ---- O += P V (warp: 16 x 128, k = 64) ----
#pragma unroll
        for (int ks = 0; ks < 64; ks += 8) {
            uint32_t a[4] = {Pu[pA0 + ks + t], Pu[pA1 + ks + t],
                             Pu[pA0 + ks + t + 4], Pu[pA1 + ks + t + 4]};
#pragma unroll
            for (int nt = 0; nt < 16; ++nt) {
                uint32_t bb[2] = {Vu[(ks + t) * SV + nt * 8 + g],
                                  Vu[(ks + t + 4) * SV + nt * 8 + g]};
                mma_tf32_16n8k8(o_[nt], a, bb);
            }
        }
        __syncthreads();   // Vs free for next iteration's cp.async
    }

    // ---- epilogue ----
    float i0 = 1.0f / l0, i1 = 1.0f / l1;
    size_t row0 = (size_t)(b * QL + q0 + 16 * w + g);
    size_t row1 = row0 + 8;
#pragma unroll
    for (int nt = 0; nt < 16; ++nt) {
        int col = h * HD + nt * 8 + c2;
        float2 v0 = {o_[nt][0] * i0, o_[nt][1] * i0};
        float2 v1 = {o_[nt][2] * i1, o_[nt][3] * i1};
        *(float2*)&g_att[row0 * HIDN + col] = v0;
        *(float2*)&g_att[row1 * HIDN + col] = v1;
    }
}

// ======================================================================
extern "C" void kernel_launch(void* const* d_in, const int* in_sizes, int n_in,
                              void* d_out, int out_size)
{
    (void)in_sizes; (void)n_in; (void)out_size;
    const float* hidden = (const float*)d_in[0];
    const float* pastk  = (const float*)d_in[1];
    const float* pastv  = (const float*)d_in[2];
    const int*   mask   = (const int*)  d_in[3];
    const float* Wq = (const float*)d_in[4];
    const float* bq = (const float*)d_in[5];
    const float* Wk = (const float*)d_in[6];
    const float* bk = (const float*)d_in[7];
    const float* Wv = (const float*)d_in[8];
    const float* bv = (const float*)d_in[9];
    const float* Wo = (const float*)d_in[10];
    const float* bo = (const float*)d_in[11];
    float* out = (float*)d_out;

    float *qp, *kp, *vp, *ap;
    cudaGetSymbolAddress((void**)&qp, g_q);
    cudaGetSymbolAddress((void**)&kp, g_k);
    cudaGetSymbolAddress((void**)&vp, g_v);
    cudaGetSymbolAddress((void**)&ap, g_att);

    cudaFuncSetAttribute(attn_mma, cudaFuncAttributeMaxDynamicSharedMemorySize, ATTN2_SMEM);

    const float alpha_q = 0.08838834764831845f;  // SCALING / sqrt(HEAD_DIM)
    dim3 blk(256);

    // QKV projections (tf32 tensor cores)
    gemm_mma<<<dim3(HIDN / 128, MROWS / 128), blk>>>(hidden, Wq, bq, qp, HIDN, HIDN, alpha_q);
    gemm_mma<<<dim3((NKV * HD) / 128, MROWS / 128), blk>>>(hidden, Wk, bk, kp, NKV * HD, HIDN, 1.0f);
    gemm_mma<<<dim3((NKV * HD) / 128, MROWS / 128), blk>>>(hidden, Wv, bv, vp, NKV * HD, HIDN, 1.0f);

    // attention (tf32 tensor cores, cp.async pipelined)
    attn_mma<<<dim3(QL / 128, NH, BB), blk, ATTN2_SMEM>>>(pastk, pastv, mask);

    // output projection
    gemm_mma<<<dim3(HIDN / 128, MROWS / 128), blk>>>(ap, Wo, bo, out, HIDN, HIDN, 1.0f);
}

// round 15
// speedup vs baseline: 4.9711x; 1.0007x over previous
#include <cuda_runtime.h>
#include <cstdint>
#include <math.h>

#define HIDN 4096
#define NH   32
#define NKV  8
#define HD   128
#define BB   4
#define QL   1024
#define PAST 1024
#define SKV  2048
#define MROWS (BB*QL)   /* 4096 */

// -------- scratch (device globals; no allocation allowed) --------
__device__ float g_q[(size_t)MROWS * HIDN];        // [B*Sq, H*D]  (tf32-rounded)
__device__ float g_k[(size_t)MROWS * (NKV * HD)];  // (tf32-rounded)
__device__ float g_v[(size_t)MROWS * (NKV * HD)];  // (tf32-rounded)
__device__ float g_att[(size_t)MROWS * HIDN];      // (tf32-rounded)
// pre-rounded copies of harness inputs
__device__ float t_hid[(size_t)MROWS * HIDN];
__device__ float t_wq[(size_t)HIDN * HIDN];
__device__ float t_wk[(size_t)(NKV * HD) * HIDN];
__device__ float t_wv[(size_t)(NKV * HD) * HIDN];
__device__ float t_wo[(size_t)HIDN * HIDN];
__device__ float t_pk[(size_t)BB * NKV * PAST * HD];
__device__ float t_pv[(size_t)BB * NKV * PAST * HD];

// ======================================================================
// helpers
// ======================================================================
__device__ __forceinline__ uint32_t smem_u32(const void* p) {
    uint32_t a;
    asm("{ .reg .u64 t; cvta.to.shared.u64 t, %1; cvt.u32.u64 %0, t; }" : "=r"(a) : "l"(p));
    return a;
}

__device__ __forceinline__ void cp_async16(uint32_t s, const void* g) {
    asm volatile("cp.async.cg.shared.global [%0], [%1], 16;" :: "r"(s), "l"(g) : "memory");
}

__device__ __forceinline__ uint32_t f2tf32(float x) {
    uint32_t r;
    asm("cvt.rna.tf32.f32 %0, %1;" : "=r"(r) : "f"(x));
    return r;
}
__device__ __forceinline__ float f2tf32f(float x) { return __uint_as_float(f2tf32(x)); }

__device__ __forceinline__ void mma_tf32_16n8k8(float* c, const uint32_t* a, const uint32_t* b) {
    asm volatile(
        "mma.sync.aligned.m16n8k8.row.col.f32.tf32.tf32.f32 "
        "{%0,%1,%2,%3}, {%4,%5,%6,%7}, {%8,%9}, {%0,%1,%2,%3};"
        : "+f"(c[0]), "+f"(c[1]), "+f"(c[2]), "+f"(c[3])
        : "r"(a[0]), "r"(a[1]), "r"(a[2]), "r"(a[3]), "r"(b[0]), "r"(b[1]));
}

// ======================================================================
// elementwise RNA-tf32 pre-rounding pass
// ======================================================================
__global__ __launch_bounds__(256) void round_tf32(
    const float4* __restrict__ in, float4* __restrict__ out, int n4)
{
    int i = blockIdx.x * blockDim.x + threadIdx.x;
    if (i < n4) {
        float4 v = in[i];
        float4 o = {f2tf32f(v.x), f2tf32f(v.y), f2tf32f(v.z), f2tf32f(v.w)};
        out[i] = o;
    }
}

// ======================================================================
// tf32 mma.sync GEMM-NT on PRE-ROUNDED operands (no CVT in hot loop).
// C[m,n] = alpha*( sum_k A[m,k]*W[n,k] + bias[n] ); rnd=1 -> round output.
// 128x128 tile, BK=16, 8 warps, double-buffered cp.async, 2 CTA/SM.
// ======================================================================
#define SA 20

__global__ __launch_bounds__(256, 2) void gemm_mma(
    const float* __restrict__ A, const float* __restrict__ W,
    const float* __restrict__ bias, float* __restrict__ C,
    int ldc, int K, float alpha, int rnd)
{
    __shared__ float As[2][128][SA];
    __shared__ float Bs[2][128][SA];

    const int tid  = threadIdx.x;
    const int lane = tid & 31, w = tid >> 5;
    const int g = lane >> 2, t = lane & 3;
    const int wm = (w & 1) * 64, wn = (w >> 1) * 32;
    const int bm = blockIdx.y * 128, bn = blockIdx.x * 128;

    const int r  = tid >> 2;
    const int c4 = (tid & 3) << 2;

    const float* aBase = A + (size_t)(bm + r) * K + c4;
    const float* bBase = W + (size_t)(bn + r) * K + c4;
    const size_t rowskip = (size_t)64 * K;

    float acc[4][4][4];
#pragma unroll
    for (int mi = 0; mi < 4; ++mi)
#pragma unroll
        for (int ni = 0; ni < 4; ++ni)
#pragma unroll
            for (int e = 0; e < 4; ++e) acc[mi][ni][e] = 0.f;

    const int kiters = K >> 4;

    {
        cp_async16(smem_u32(&As[0][r][c4]), aBase);
        cp_async16(smem_u32(&As[0][r + 64][c4]), aBase + rowskip);
        cp_async16(smem_u32(&Bs[0][r][c4]), bBase);
        cp_async16(smem_u32(&Bs[0][r + 64][c4]), bBase + rowskip);
        asm volatile("cp.async.commit_group;" ::: "memory");
    }

    for (int it = 0; it < kiters; ++it) {
        const int buf = it & 1;
        if (it + 1 < kiters) {
            const float* ag = aBase + (size_t)(it + 1) * 16;
            const float* bg = bBase + (size_t)(it + 1) * 16;
            cp_async16(smem_u32(&As[buf ^ 1][r][c4]), ag);
            cp_async16(smem_u32(&As[buf ^ 1][r + 64][c4]), ag + rowskip);
            cp_async16(smem_u32(&Bs[buf ^ 1][r][c4]), bg);
            cp_async16(smem_u32(&Bs[buf ^ 1][r + 64][c4]), bg + rowskip);
            asm volatile("cp.async.commit_group;" ::: "memory");
            asm volatile("cp.async.wait_group 1;" ::: "memory");
        } else {
            asm volatile("cp.async.wait_group 0;" ::: "memory");
        }
        __syncthreads();

#pragma unroll
        for (int ks = 0; ks < 16; ks += 8) {
            uint32_t af[4][4], bf[4][2];
#pragma unroll
            for (int mi = 0; mi < 4; ++mi) {
                const int mr = wm + 16 * mi + g;
                af[mi][0] = __float_as_uint(As[buf][mr][ks + t]);
                af[mi][1] = __float_as_uint(As[buf][mr + 8][ks + t]);
                af[mi][2] = __float_as_uint(As[buf][mr][ks + t + 4]);
                af[mi][3] = __float_as_uint(As[buf][mr + 8][ks + t + 4]);
            }
#pragma unroll
            for (int ni = 0; ni < 4; ++ni) {
                const int nr = wn + 8 * ni + g;
                bf[ni][0] = __float_as_uint(Bs[buf][nr][ks + t]);
                bf[ni][1] = __float_as_uint(Bs[buf][nr][ks + t + 4]);
            }
#pragma unroll
            for (int mi = 0; mi < 4; ++mi)
#pragma unroll
                for (int ni = 0; ni < 4; ++ni)
                    mma_tf32_16n8k8(acc[mi][ni], af[mi], bf[ni]);
        }
        __syncthreads();
    }

#pragma unroll
    for (int mi = 0; mi < 4; ++mi) {
        const int row0 = bm + wm + 16 * mi + g;
#pragma unroll
        for (int ni = 0; ni < 4; ++ni) {
            const int col = bn + wn + 8 * ni + 2 * t;
            const float b0 = bias[col], b1 = bias[col + 1];
            float2 v0, v1;
            v0.x = alpha * (acc[mi][ni][0] + b0);
            v0.y = alpha * (acc[mi][ni][1] + b1);
            v1.x = alpha * (acc[mi][ni][2] + b0);
            v1.y = alpha * (acc[mi][ni][3] + b1);
            if (rnd) {
                v0.x = f2tf32f(v0.x); v0.y = f2tf32f(v0.y);
                v1.x = f2tf32f(v1.x); v1.y = f2tf32f(v1.y);
            }
            *(float2*)&C[(size_t)row0 * ldc + col]       = v0;
            *(float2*)&C[(size_t)(row0 + 8) * ldc + col] = v1;
        }
    }
}

// ======================================================================
// Tensor-core flash attention, cp.async K/V pipeline, all inputs
// pre-rounded to tf32 (no conversion passes in the loop).
// ======================================================================
#define SQ 132
#define SV 136
#define SP 68
#define NKT (SKV / 64)
#define ATTN2_FLOATS (128*SQ + 2*64*SQ + 64*SV + 128*SP)
#define ATTN2_SMEM (ATTN2_FLOATS * 4)   /* 204800 B */

__global__ __launch_bounds__(256, 1) void attn_mma(
    const float* __restrict__ pastk, const float* __restrict__ pastv,
    const int* __restrict__ mask)
{
    extern __shared__ __align__(16) float sm[];
    float* Qs = sm;                    // [128][SQ]
    float* Kb = Qs + 128 * SQ;         // [2][64][SQ]
    float* Vs = Kb + 2 * 64 * SQ;      // [64][SV]
    float* Ps = Vs + 64 * SV;          // [128][SP]

    const int tid = threadIdx.x;
    const int lane = tid & 31, w = tid >> 5;
    const int g = lane >> 2, t = lane & 3;
    const int c2 = 2 * t;
    const int qt = blockIdx.x, h = blockIdx.y, b = blockIdx.z;
    const int hkv = h >> 2;
    const int q0 = qt * 128;

    const int lr = tid >> 5;             // base row 0..7 (step 8)
    const int lc4 = (tid & 31) << 2;     // col 0,4,...,124

    // ---- prefetch K tile 0 ----
    {
#pragma unroll
        for (int rr = 0; rr < 8; ++rr) {
            int jg = lr + rr * 8;
            const float* ksrc;
            if (jg < PAST)
                ksrc = pastk + ((size_t)(b * NKV + hkv) * PAST + jg) * HD + lc4;
            else
                ksrc = g_k + (size_t)(b * QL + (jg - PAST)) * (NKV * HD) + hkv * HD + lc4;
            cp_async16(smem_u32(&Kb[(lr + rr * 8) * SQ + lc4]), ksrc);
        }
        asm volatile("cp.async.commit_group;" ::: "memory");
    }

    // ---- load Q tile (already tf32-rounded) ----
    for (int e = tid; e < 128 * 32; e += 256) {
        int r = e >> 5, c4 = (e & 31) << 2;
        *(float4*)&Qs[r * SQ + c4] =
            *(const float4*)(g_q + (size_t)(b * QL + q0 + r) * HIDN + h * HD + c4);
    }

    float m0 = -1e30f, m1 = -1e30f, l0 = 0.f, l1 = 0.f;
    float o_[16][4];
#pragma unroll
    for (int nt = 0; nt < 16; ++nt)
#pragma unroll
        for (int e = 0; e < 4; ++e) o_[nt][e] = 0.f;

    const uint32_t* Qu = (const uint32_t*)Qs;
    const uint32_t* Vu = (const uint32_t*)Vs;
    const uint32_t* Pu = (const uint32_t*)Ps;

    const int rA0 = (16 * w + g) * SQ;
    const int rA1 = (16 * w + g + 8) * SQ;
    const int pA0 = (16 * w + g) * SP;
    const int pA1 = (16 * w + g + 8) * SP;

    for (int kt = 0; kt < NKT; ++kt) {
        const int kv0 = kt * 64;
        const int cur = kt & 1;
        float* Kcur = Kb + cur * 64 * SQ;
        const uint32_t* Ku = (const uint32_t*)Kcur;

        // ---- issue V_kt ----
#pragma unroll
        for (int rr = 0; rr < 8; ++rr) {
            int jg = kv0 + lr + rr * 8;
            const float* vsrc;
            if (jg < PAST)
                vsrc = pastv + ((size_t)(b * NKV + hkv) * PAST + jg) * HD + lc4;
            else
                vsrc = g_v + (size_t)(b * QL + (jg - PAST)) * (NKV * HD) + hkv * HD + lc4;
            cp_async16(smem_u32(&Vs[(lr + rr * 8) * SV + lc4]), vsrc);
        }
        asm volatile("cp.async.commit_group;" ::: "memory");

        // ---- issue K_{kt+1} (empty group on last iter) ----
        if (kt + 1 < NKT) {
            float* Knxt = Kb + (cur ^ 1) * 64 * SQ;
#pragma unroll
            for (int rr = 0; rr < 8; ++rr) {
                int jg = kv0 + 64 + lr + rr * 8;
                const float* ksrc;
                if (jg < PAST)
                    ksrc = pastk + ((size_t)(b * NKV + hkv) * PAST + jg) * HD + lc4;
                else
                    ksrc = g_k + (size_t)(b * QL + (jg - PAST)) * (NKV * HD) + hkv * HD + lc4;
                cp_async16(smem_u32(&Knxt[(lr + rr * 8) * SQ + lc4]), ksrc);
            }
        }
        asm volatile("cp.async.commit_group;" ::: "memory");

        // ---- mask values into registers ----
        int2 mv[8];
#pragma unroll
        for (int nt = 0; nt < 8; ++nt)
            mv[nt] = *(const int2*)&mask[b * SKV + kv0 + nt * 8 + c2];

        // ---- wait K_kt (leave V_kt + K_{kt+1} pending) ----
        asm volatile("cp.async.wait_group 2;" ::: "memory");
        __syncthreads();

        // ---- S = Q K^T (warp: 16 x 64); V_kt load in flight ----
        float s[8][4];
#pragma unroll
        for (int nt = 0; nt < 8; ++nt)
#pragma unroll
            for (int e = 0; e < 4; ++e) s[nt][e] = 0.f;

#pragma unroll
        for (int ks = 0; ks < 128; ks += 8) {
            uint32_t a[4] = {Qu[rA0 + ks + t], Qu[rA1 + ks + t],
                             Qu[rA0 + ks + t + 4], Qu[rA1 + ks + t + 4]};
#pragma unroll
            for (int nt = 0; nt < 8; ++nt) {
                uint32_t bb[2] = {Ku[(nt * 8 + g) * SQ + ks + t],
                                  Ku[(nt * 8 + g) * SQ + ks + t + 4]};
                mma_tf32_16n8k8(s[nt], a, bb);
            }
        }

        // ---- mask + online softmax ----
        float rm0 = -1e30f, rm1 = -1e30f;
#pragma unroll
        for (int nt = 0; nt < 8; ++nt) {
            float mk0 = (mv[nt].x == 0) ? 0.0f : -1e9f;
            float mk1 = (mv[nt].y == 0) ? 0.0f : -1e9f;
            s[nt][0] += mk0; s[nt][1] += mk1;
            s[nt][2] += mk0; s[nt][3] += mk1;
            rm0 = fmaxf(rm0, fmaxf(s[nt][0], s[nt][1]));
            rm1 = fmaxf(rm1, fmaxf(s[nt][2], s[nt][3]));
        }
        rm0 = fmaxf(rm0, __shfl_xor_sync(0xffffffffu, rm0, 1));
        rm0 = fmaxf(rm0, __shfl_xor_sync(0xffffffffu, rm0, 2));
        rm1 = fmaxf(rm1, __shfl_xor_sync(0xffffffffu, rm1, 1));
        rm1 = fmaxf(rm1, __shfl_xor_sync(0xffffffffu, rm1, 2));

        float mn0 = fmaxf(m0, rm0), mn1 = fmaxf(m1, rm1);
        float corr0 = __expf(m0 - mn0), corr1 = __expf(m1 - mn1);
        float rs0 = 0.f, rs1 = 0.f;
#pragma unroll
        for (int nt = 0; nt < 8; ++nt) {
            float p0 = __expf(s[nt][0] - mn0);
            float p1 = __expf(s[nt][1] - mn0);
            float p2 = __expf(s[nt][2] - mn1);
            float p3 = __expf(s[nt][3] - mn1);
            rs0 += p0 + p1; rs1 += p2 + p3;
            Ps[pA0 + nt * 8 + c2]     = f2tf32f(p0);
            Ps[pA0 + nt * 8 + c2 + 1] = f2tf32f(p1);
            Ps[pA1 + nt * 8 + c2]     = f2tf32f(p2);
            Ps[pA1 + nt * 8 + c2 + 1] = f2tf32f(p3);
        }
        rs0 += __shfl_xor_sync(0xffffffffu, rs0, 1);
        rs0 += __shfl_xor_sync(0xffffffffu, rs0, 2);
        rs1 += __shfl_xor_sync(0xffffffffu, rs1, 1);
        rs1 += __shfl_xor_sync(0xffffffffu, rs1, 2);

        l0 = l0 * corr0 + rs0; m0 = mn0;
        l1 = l1 * corr1 + rs1; m1 = mn1;
#pragma unroll
        for (int nt = 0; nt < 16; ++nt) {
            o_[nt][0] *= corr0; o_[nt][1] *= corr0;
            o_[nt][2] *= corr1; o_[nt][3] *= corr1;
        }
        __syncwarp();

        // ---- wait V_kt (leave K_{kt+1} pending) ----
        asm volatile("cp.async.wait_group 1;" ::: "memory");
        __syncthreads();

        // ---- O += P V (warp: 16 x 128, k = 64) ----
#pragma unroll
        for (int ks = 0; ks < 64; ks += 8) {
            uint32_t a[4] = {Pu[pA0 + ks + t], Pu[pA1 + ks + t],
                             Pu[pA0 + ks + t + 4], Pu[pA1 + ks + t + 4]};
#pragma unroll
            for (int nt = 0; nt < 16; ++nt) {
                uint32_t bb[2] = {Vu[(ks + t) * SV + nt * 8 + g],
                                  Vu[(ks + t + 4) * SV + nt * 8 + g]};
                mma_tf32_16n8k8(o_[nt], a, bb);
            }
        }
        __syncthreads();   // Vs free for next iteration's cp.async
    }

    // ---- epilogue: normalize, round to tf32 for the O-projection ----
    float i0 = 1.0f / l0, i1 = 1.0f / l1;
    size_t row0 = (size_t)(b * QL + q0 + 16 * w + g);
    size_t row1 = row0 + 8;
#pragma unroll
    for (int nt = 0; nt < 16; ++nt) {
        int col = h * HD + nt * 8 + c2;
        float2 v0 = {f2tf32f(o_[nt][0] * i0), f2tf32f(o_[nt][1] * i0)};
        float2 v1 = {f2tf32f(o_[nt][2] * i1), f2tf32f(o_[nt][3] * i1)};
        *(float2*)&g_att[row0 * HIDN + col] = v0;
        *(float2*)&g_att[row1 * HIDN + col] = v1;
    }
}

// ======================================================================
extern "C" void kernel_launch(void* const* d_in, const int* in_sizes, int n_in,
                              void* d_out, int out_size)
{
    (void)in_sizes; (void)n_in; (void)out_size;
    const float* hidden = (const float*)d_in[0];
    const float* pastk  = (const float*)d_in[1];
    const float* pastv  = (const float*)d_in[2];
    const int*   mask   = (const int*)  d_in[3];
    const float* Wq = (const float*)d_in[4];
    const float* bq = (const float*)d_in[5];
    const float* Wk = (const float*)d_in[6];
    const float* bk = (const float*)d_in[7];
    const float* Wv = (const float*)d_in[8];
    const float* bv = (const float*)d_in[9];
    const float* Wo = (const float*)d_in[10];
    const float* bo = (const float*)d_in[11];
    float* out = (float*)d_out;

    float *qp, *kp, *vp, *ap, *thid, *twq, *twk, *twv, *two, *tpk, *tpv;
    cudaGetSymbolAddress((void**)&qp, g_q);
    cudaGetSymbolAddress((void**)&kp, g_k);
    cudaGetSymbolAddress((void**)&vp, g_v);
    cudaGetSymbolAddress((void**)&ap, g_att);
    cudaGetSymbolAddress((void**)&thid, t_hid);
    cudaGetSymbolAddress((void**)&twq, t_wq);
    cudaGetSymbolAddress((void**)&twk, t_wk);
    cudaGetSymbolAddress((void**)&twv, t_wv);
    cudaGetSymbolAddress((void**)&two, t_wo);
    cudaGetSymbolAddress((void**)&tpk, t_pk);
    cudaGetSymbolAddress((void**)&tpv, t_pv);

    cudaFuncSetAttribute(attn_mma, cudaFuncAttributeMaxDynamicSharedMemorySize, ATTN2_SMEM);

    const float alpha_q = 0.08838834764831845f;  // SCALING / sqrt(HEAD_DIM)
    dim3 blk(256);

    // ---- pre-round harness inputs to tf32 (RNA), once ----
    auto rr = [&](const float* src, float* dst, size_t n) {
        int n4 = (int)(n / 4);
        round_tf32<<<(n4 + 255) / 256, 256>>>((const float4*)src, (float4*)dst, n4);
    };
    rr(hidden, thid, (size_t)MROWS * HIDN);
    rr(Wq, twq, (size_t)HIDN * HIDN);
    rr(Wk, twk, (size_t)(NKV * HD) * HIDN);
    rr(Wv, twv, (size_t)(NKV * HD) * HIDN);
    rr(Wo, two, (size_t)HIDN * HIDN);
    rr(pastk, tpk, (size_t)BB * NKV * PAST * HD);
    rr(pastv, tpv, (size_t)BB * NKV * PAST * HD);

    // ---- QKV projections (pre-rounded A/B; outputs rounded for attn) ----
    gemm_mma<<<dim3(HIDN / 128, MROWS / 128), blk>>>(thid, twq, bq, qp, HIDN, HIDN, alpha_q, 1);
    gemm_mma<<<dim3((NKV * HD) / 128, MROWS / 128), blk>>>(thid, twk, bk, kp, NKV * HD, HIDN, 1.0f, 1);
    gemm_mma<<<dim3((NKV * HD) / 128, MROWS / 128), blk>>>(thid, twv, bv, vp, NKV * HD, HIDN, 1.0f, 1);

    // ---- attention (all operands pre-rounded) ----
    attn_mma<<<dim3(QL / 128, NH, BB), blk, ATTN2_SMEM>>>(tpk, tpv, mask);

    // ---- output projection (fp32 output, no rounding) ----
    gemm_mma<<<dim3(HIDN / 128, MROWS / 128), blk>>>(ap, two, bo, out, HIDN, HIDN, 1.0f, 0);
}